// round 9
// baseline (speedup 1.0000x reference)
#include <cuda_runtime.h>
#include <cuda_bf16.h>
#include <math.h>
#include <stdint.h>

#define NROWS   262144
#define HID     512
#define NHEADS  8
#define NG      1024
#define NHID1   256
#define LN_EPS  1e-5f
#define SM_EPS  1e-8f

// ---- HMMA tiling ----
#define TM      128          // rows per CTA
#define TN      256          // full N
#define BK      32           // K per chunk
#define NCH     16           // 512 / 32
#define NTHR    256          // 8 warps, warp tile 64x64 (grid 2x4)

// A smem row stride: 32 bf16 + 8 pad = 40 bf16 = 80 B
#define ARS     80
// B smem row stride: 256 bf16 + 8 pad = 264 bf16 = 528 B
#define BRS     528

// per-buffer byte offsets
#define OFF_AH   0
#define OFF_AL   10240        // 128*80
#define OFF_BH   20480
#define OFF_BL   37376        // +32*528
#define BUF_SZ   54272        // per stage
// tail region
#define OFF_W2   108544       // 256*8 f32 = 8192
#define OFF_B1   116736       // 256 f32 = 1024
#define OFF_MU   117760       // 128 f32 = 512
#define OFF_RS   118272       // 128 f32 = 512
#define OFF_LG   118784       // 128*8 f32 = 4096
#define OFF_GS   122880       // 512 f32 = 2048
#define OFF_BT   124928       // 512 f32 = 2048
#define SMEM_TOT 126976

static __device__ float g_logits[(size_t)NROWS * NHEADS];
static __device__ float g_maxv[NG * NHEADS];
static __device__ float g_denv[NG * NHEADS];
static __device__ int   g_off[NG + 1];
// W1 hi/lo bf16 split, row-major [512(k)][256(n)]
static __device__ __nv_bfloat16 g_Bhi[HID * NHID1];
static __device__ __nv_bfloat16 g_Blo[HID * NHID1];

// ---------------------------------------------------------------------------
__device__ __forceinline__ uint32_t smem_u32(const void* p)
{
    uint32_t a;
    asm("{ .reg .u64 t; cvta.to.shared.u64 t, %1; cvt.u32.u64 %0, t; }"
        : "=r"(a) : "l"(p));
    return a;
}

__device__ __forceinline__ void ldsm4(uint32_t* r, uint32_t addr)
{
    asm volatile("ldmatrix.sync.aligned.m8n8.x4.shared.b16 {%0,%1,%2,%3}, [%4];"
                 : "=r"(r[0]), "=r"(r[1]), "=r"(r[2]), "=r"(r[3]) : "r"(addr));
}

__device__ __forceinline__ void ldsm4t(uint32_t* r, uint32_t addr)
{
    asm volatile("ldmatrix.sync.aligned.m8n8.x4.trans.shared.b16 {%0,%1,%2,%3}, [%4];"
                 : "=r"(r[0]), "=r"(r[1]), "=r"(r[2]), "=r"(r[3]) : "r"(addr));
}

__device__ __forceinline__ void mma16816(float* d, const uint32_t* a, const uint32_t* b)
{
    asm volatile(
        "mma.sync.aligned.m16n8k16.row.col.f32.bf16.bf16.f32 "
        "{%0,%1,%2,%3}, {%4,%5,%6,%7}, {%8,%9}, {%0,%1,%2,%3};"
        : "+f"(d[0]), "+f"(d[1]), "+f"(d[2]), "+f"(d[3])
        : "r"(a[0]), "r"(a[1]), "r"(a[2]), "r"(a[3]), "r"(b[0]), "r"(b[1]));
}

__device__ __forceinline__ void cp16(uint32_t dst, const void* src)
{
    asm volatile("cp.async.cg.shared.global [%0], [%1], 16;"
                 :: "r"(dst), "l"(src) : "memory");
}
#define CP_COMMIT() asm volatile("cp.async.commit_group;" ::: "memory")
#define CP_WAIT0()  asm volatile("cp.async.wait_group 0;" ::: "memory")

__device__ __forceinline__ unsigned pk(__nv_bfloat16 a, __nv_bfloat16 b)
{
    __nv_bfloat162 t = __halves2bfloat162(a, b);
    return *reinterpret_cast<unsigned*>(&t);
}

// transform one float4 of x -> LN -> bf16 hi/lo, store 8B each
__device__ __forceinline__ void xf_store(char* smc, uint32_t base, int row, int kq,
                                         float4 v, float mu, float rs,
                                         float4 gv, float4 bv)
{
    float n0 = (v.x - mu) * rs * gv.x + bv.x;
    float n1 = (v.y - mu) * rs * gv.y + bv.y;
    float n2 = (v.z - mu) * rs * gv.z + bv.z;
    float n3 = (v.w - mu) * rs * gv.w + bv.w;
    __nv_bfloat16 h0 = __float2bfloat16(n0), h1 = __float2bfloat16(n1);
    __nv_bfloat16 h2 = __float2bfloat16(n2), h3 = __float2bfloat16(n3);
    *reinterpret_cast<uint2*>(smc + base + OFF_AH + row * ARS + kq * 2) =
        make_uint2(pk(h0, h1), pk(h2, h3));
    *reinterpret_cast<uint2*>(smc + base + OFF_AL + row * ARS + kq * 2) =
        make_uint2(pk(__float2bfloat16(n0 - __bfloat162float(h0)),
                      __float2bfloat16(n1 - __bfloat162float(h1))),
                   pk(__float2bfloat16(n2 - __bfloat162float(h2)),
                      __float2bfloat16(n3 - __bfloat162float(h3))));
}

// ---------------------------------------------------------------------------
__global__ void k_init(float* __restrict__ ent)
{
    if (threadIdx.x == 0) *ent = 0.f;
}

__global__ void k_bounds(const int* __restrict__ batch)
{
    int i = blockIdx.x * blockDim.x + threadIdx.x;
    if (i >= NROWS) return;
    int cur  = batch[i];
    int prev = (i == 0) ? -1 : batch[i - 1];
    for (int g = prev + 1; g <= cur; ++g) g_off[g] = i;
    if (i == NROWS - 1)
        for (int g = cur + 1; g <= NG; ++g) g_off[g] = NROWS;
}

__global__ void k_prepw(const float* __restrict__ W1)
{
    int i = blockIdx.x * 256 + threadIdx.x;
    float v = W1[i];
    __nv_bfloat16 h = __float2bfloat16(v);
    __nv_bfloat16 l = __float2bfloat16(v - __bfloat162float(h));
    g_Bhi[i] = h;
    g_Blo[i] = l;
}

// ---------------------------------------------------------------------------
// Fused LayerNorm + GEMM1 (bf16 HMMA, 3-product hi/lo split) + SiLU + GEMM2
// 8 warps, warp tile 64x64
// ---------------------------------------------------------------------------
__global__ __launch_bounds__(NTHR, 1)
void k_logits_mma(const float* __restrict__ x,
                  const float* __restrict__ gamma,
                  const float* __restrict__ beta,
                  const float* __restrict__ b1,
                  const float* __restrict__ W2,
                  const float* __restrict__ b2)
{
    extern __shared__ char smc[];
    float* smf = reinterpret_cast<float*>(smc);
    const uint32_t sb = smem_u32(smc);

    const int tid  = threadIdx.x;
    const int wid  = tid >> 5;
    const int lane = tid & 31;
    const int m_base = blockIdx.x * TM;

    // tail-region fills
    for (int i = tid; i < 2048; i += NTHR) smf[OFF_W2 / 4 + i] = W2[i];
    if (tid < 256) smf[OFF_B1 / 4 + tid] = b1[tid];
    for (int i = tid; i < HID; i += NTHR) {
        smf[OFF_GS / 4 + i] = gamma[i];
        smf[OFF_BT / 4 + i] = beta[i];
    }
    for (int i = tid; i < TM * NHEADS; i += NTHR)
        smf[OFF_LG / 4 + i] = b2[i & 7];

    // ---- LayerNorm stats: 2 threads per row ----
    {
        int row = tid >> 1, part = tid & 1;
        const float4* xr = reinterpret_cast<const float4*>(
            x + (size_t)(m_base + row) * HID) + part * 64;
        float s = 0.f, s2 = 0.f;
        #pragma unroll 8
        for (int i = 0; i < 64; ++i) {
            float4 v = __ldg(xr + i);
            s  += v.x + v.y + v.z + v.w;
            s2 += v.x * v.x + v.y * v.y + v.z * v.z + v.w * v.w;
        }
        s  += __shfl_xor_sync(0xffffffffu, s, 1);
        s2 += __shfl_xor_sync(0xffffffffu, s2, 1);
        if (!part) {
            float m = s * (1.f / HID);
            float v = s2 * (1.f / HID) - m * m;
            smf[OFF_MU / 4 + row] = m;
            smf[OFF_RS / 4 + row] = rsqrtf(v + LN_EPS);
        }
    }
    __syncthreads();

    // per-thread A geometry: 4 slots, rows tid>>3 + {0,32,64,96}, same kq
    const int a_kq = (tid & 7) * 4;
    int   a_row[4];
    float a_mu[4], a_rs[4];
    const float* xp[4];
    #pragma unroll
    for (int s = 0; s < 4; ++s) {
        a_row[s] = (tid >> 3) + s * 32;
        a_mu[s]  = smf[OFF_MU / 4 + a_row[s]];
        a_rs[s]  = smf[OFF_RS / 4 + a_row[s]];
        xp[s]    = x + (size_t)(m_base + a_row[s]) * HID + a_kq;
    }

    // B copy geometry: 4 float4 slots per buffer half
    int b_r[4], b_c[4];
    #pragma unroll
    for (int s = 0; s < 4; ++s) {
        int j = tid + s * 256;
        b_r[s] = j >> 5;
        b_c[s] = (j & 31) * 16;
    }

    // warp MMA geometry: warp grid 2x4, warp tile 64x64
    const int wm = (wid >> 2) * 64;
    const int wn = (wid & 3) * 64;
    const uint32_t a_lds = (uint32_t)((wm + (lane & 15)) * ARS + (lane >> 4) * 16);
    const uint32_t b_lds = (uint32_t)((lane & 15) * BRS + (wn + (lane >> 4) * 8) * 2);

    float acc[4][8][4];
    #pragma unroll
    for (int mt = 0; mt < 4; ++mt)
        #pragma unroll
        for (int nt = 0; nt < 8; ++nt)
            #pragma unroll
            for (int e = 0; e < 4; ++e) acc[mt][nt][e] = 0.f;

    float4 xr[4];

    // ---- prologue: fill buffer 0 (chunk 0) ----
    {
        #pragma unroll
        for (int s = 0; s < 4; ++s) {
            cp16(sb + OFF_BH + b_r[s] * BRS + b_c[s],
                 (const char*)g_Bhi + b_r[s] * 512 + b_c[s]);
            cp16(sb + OFF_BL + b_r[s] * BRS + b_c[s],
                 (const char*)g_Blo + b_r[s] * 512 + b_c[s]);
        }
        CP_COMMIT();
        #pragma unroll
        for (int s = 0; s < 4; ++s)
            xr[s] = __ldg(reinterpret_cast<const float4*>(xp[s]));
        const float4 gv = *reinterpret_cast<const float4*>(&smf[OFF_GS / 4 + a_kq]);
        const float4 bv = *reinterpret_cast<const float4*>(&smf[OFF_BT / 4 + a_kq]);
        #pragma unroll
        for (int s = 0; s < 4; ++s)
            xf_store(smc, 0, a_row[s], a_kq, xr[s], a_mu[s], a_rs[s], gv, bv);
        CP_WAIT0();
    }
    __syncthreads();

    // ---- mainloop ----
    for (int t = 0; t < NCH; ++t) {
        const uint32_t bufc = (uint32_t)((t & 1) * BUF_SZ);
        const uint32_t bufn = (uint32_t)(((t + 1) & 1) * BUF_SZ);
        const bool more = (t < NCH - 1);

        if (more) {
            const char* gh = (const char*)g_Bhi + (size_t)(t + 1) * 32 * 512;
            const char* gl = (const char*)g_Blo + (size_t)(t + 1) * 32 * 512;
            #pragma unroll
            for (int s = 0; s < 4; ++s) {
                cp16(sb + bufn + OFF_BH + b_r[s] * BRS + b_c[s], gh + b_r[s] * 512 + b_c[s]);
                cp16(sb + bufn + OFF_BL + b_r[s] * BRS + b_c[s], gl + b_r[s] * 512 + b_c[s]);
            }
            CP_COMMIT();
            #pragma unroll
            for (int s = 0; s < 4; ++s)
                xr[s] = __ldg(reinterpret_cast<const float4*>(xp[s] + (t + 1) * BK));
        }

        // MMA ks = 0
        {
            uint32_t ah[4][4], al[4][4];
            #pragma unroll
            for (int mt = 0; mt < 4; ++mt) {
                uint32_t ao = sb + bufc + a_lds + (uint32_t)(mt * 16 * ARS);
                ldsm4(ah[mt], ao + OFF_AH);
                ldsm4(al[mt], ao + OFF_AL);
            }
            #pragma unroll
            for (int np = 0; np < 4; ++np) {
                uint32_t bh[4], bl[4];
                uint32_t bo = sb + bufc + b_lds + (uint32_t)(np * 32);
                ldsm4t(bh, bo + OFF_BH);
                ldsm4t(bl, bo + OFF_BL);
                #pragma unroll
                for (int mt = 0; mt < 4; ++mt) {
                    mma16816(acc[mt][2 * np],     ah[mt], bh);
                    mma16816(acc[mt][2 * np],     ah[mt], bl);
                    mma16816(acc[mt][2 * np],     al[mt], bh);
                    mma16816(acc[mt][2 * np + 1], ah[mt], bh + 2);
                    mma16816(acc[mt][2 * np + 1], ah[mt], bl + 2);
                    mma16816(acc[mt][2 * np + 1], al[mt], bh + 2);
                }
            }
        }

        // transform + store A(t+1) (overlaps tensor-pipe drain of ks=0)
        if (more) {
            const int kb = (t + 1) * BK;
            const float4 gv = *reinterpret_cast<const float4*>(&smf[OFF_GS / 4 + kb + a_kq]);
            const float4 bv = *reinterpret_cast<const float4*>(&smf[OFF_BT / 4 + kb + a_kq]);
            #pragma unroll
            for (int s = 0; s < 4; ++s)
                xf_store(smc, bufn, a_row[s], a_kq, xr[s], a_mu[s], a_rs[s], gv, bv);
        }

        // MMA ks = 1
        {
            uint32_t ah[4][4], al[4][4];
            #pragma unroll
            for (int mt = 0; mt < 4; ++mt) {
                uint32_t ao = sb + bufc + a_lds + (uint32_t)(mt * 16 * ARS + 32);
                ldsm4(ah[mt], ao + OFF_AH);
                ldsm4(al[mt], ao + OFF_AL);
            }
            #pragma unroll
            for (int np = 0; np < 4; ++np) {
                uint32_t bh[4], bl[4];
                uint32_t bo = sb + bufc + b_lds + (uint32_t)(16 * BRS + np * 32);
                ldsm4t(bh, bo + OFF_BH);
                ldsm4t(bl, bo + OFF_BL);
                #pragma unroll
                for (int mt = 0; mt < 4; ++mt) {
                    mma16816(acc[mt][2 * np],     ah[mt], bh);
                    mma16816(acc[mt][2 * np],     ah[mt], bl);
                    mma16816(acc[mt][2 * np],     al[mt], bh);
                    mma16816(acc[mt][2 * np + 1], ah[mt], bh + 2);
                    mma16816(acc[mt][2 * np + 1], ah[mt], bl + 2);
                    mma16816(acc[mt][2 * np + 1], al[mt], bh + 2);
                }
            }
        }

        if (more) CP_WAIT0();
        __syncthreads();
    }

    // ---- epilogue: SiLU + GEMM2 (h @ W2), accumulate logits in smem ----
    const int g = lane >> 2, q = lane & 3;
    float pacc[8][8];
    #pragma unroll
    for (int r = 0; r < 8; ++r)
        #pragma unroll
        for (int h = 0; h < 8; ++h) pacc[r][h] = 0.f;

    #pragma unroll
    for (int nt = 0; nt < 8; ++nt) {
        const int c0 = wn + nt * 8 + q * 2;
        const float4 w0a = *reinterpret_cast<const float4*>(&smf[OFF_W2 / 4 + c0 * 8]);
        const float4 w0b = *reinterpret_cast<const float4*>(&smf[OFF_W2 / 4 + c0 * 8 + 4]);
        const float4 w1a = *reinterpret_cast<const float4*>(&smf[OFF_W2 / 4 + (c0 + 1) * 8]);
        const float4 w1b = *reinterpret_cast<const float4*>(&smf[OFF_W2 / 4 + (c0 + 1) * 8 + 4]);
        const float b1c0 = smf[OFF_B1 / 4 + c0];
        const float b1c1 = smf[OFF_B1 / 4 + c0 + 1];
        #pragma unroll
        for (int mt = 0; mt < 4; ++mt) {
            #pragma unroll
            for (int e = 0; e < 4; ++e) {
                float hv = acc[mt][nt][e] + ((e & 1) ? b1c1 : b1c0);
                float sv = hv / (1.f + __expf(-hv));
                const int r = mt * 2 + (e >> 1);
                const float4 wa = (e & 1) ? w1a : w0a;
                const float4 wb = (e & 1) ? w1b : w0b;
                pacc[r][0] += sv * wa.x; pacc[r][1] += sv * wa.y;
                pacc[r][2] += sv * wa.z; pacc[r][3] += sv * wa.w;
                pacc[r][4] += sv * wb.x; pacc[r][5] += sv * wb.y;
                pacc[r][6] += sv * wb.z; pacc[r][7] += sv * wb.w;
            }
        }
    }
    #pragma unroll
    for (int r = 0; r < 8; ++r)
        #pragma unroll
        for (int h = 0; h < 8; ++h) {
            pacc[r][h] += __shfl_xor_sync(0xffffffffu, pacc[r][h], 1);
            pacc[r][h] += __shfl_xor_sync(0xffffffffu, pacc[r][h], 2);
        }
    if (q == 0) {
        #pragma unroll
        for (int r = 0; r < 8; ++r) {
            const int row = wm + (r >> 1) * 16 + (r & 1) * 8 + g;
            #pragma unroll
            for (int h = 0; h < 8; ++h)
                atomicAdd(&smf[OFF_LG / 4 + row * 8 + h], pacc[r][h]);
        }
    }
    __syncthreads();

    if (tid < TM) {
        const float4* src = reinterpret_cast<const float4*>(&smf[OFF_LG / 4 + tid * 8]);
        float4* dst = reinterpret_cast<float4*>(g_logits + (size_t)(m_base + tid) * 8);
        dst[0] = src[0];
        dst[1] = src[1];
    }
}

// ---------------------------------------------------------------------------
__global__ void k_stats()
{
    int g = blockIdx.x;
    int s = g_off[g], e = g_off[g + 1];
    int tid = threadIdx.x, lane = tid & 31, wid = tid >> 5;
    __shared__ float red[8][8];
    __shared__ float smax[8];

    float lm[8];
    #pragma unroll
    for (int h = 0; h < 8; ++h) lm[h] = -INFINITY;
    for (int r = s + tid; r < e; r += 256) {
        const float4* lp = reinterpret_cast<const float4*>(g_logits + (size_t)r * 8);
        float4 a = lp[0], b = lp[1];
        lm[0] = fmaxf(lm[0], a.x); lm[1] = fmaxf(lm[1], a.y);
        lm[2] = fmaxf(lm[2], a.z); lm[3] = fmaxf(lm[3], a.w);
        lm[4] = fmaxf(lm[4], b.x); lm[5] = fmaxf(lm[5], b.y);
        lm[6] = fmaxf(lm[6], b.z); lm[7] = fmaxf(lm[7], b.w);
    }
    #pragma unroll
    for (int h = 0; h < 8; ++h)
        #pragma unroll
        for (int o = 16; o > 0; o >>= 1)
            lm[h] = fmaxf(lm[h], __shfl_xor_sync(0xffffffffu, lm[h], o));
    if (lane == 0)
        #pragma unroll
        for (int h = 0; h < 8; ++h) red[wid][h] = lm[h];
    __syncthreads();
    if (tid < 8) {
        float m = red[0][tid];
        #pragma unroll
        for (int w = 1; w < 8; ++w) m = fmaxf(m, red[w][tid]);
        if (!(m >= -3.0e38f)) m = 0.f;
        smax[tid] = m;
        g_maxv[g * 8 + tid] = m;
    }
    __syncthreads();

    float mx[8], ls[8];
    #pragma unroll
    for (int h = 0; h < 8; ++h) { mx[h] = smax[h]; ls[h] = 0.f; }
    for (int r = s + tid; r < e; r += 256) {
        const float4* lp = reinterpret_cast<const float4*>(g_logits + (size_t)r * 8);
        float4 a = lp[0], b = lp[1];
        ls[0] += __expf(a.x - mx[0]); ls[1] += __expf(a.y - mx[1]);
        ls[2] += __expf(a.z - mx[2]); ls[3] += __expf(a.w - mx[3]);
        ls[4] += __expf(b.x - mx[4]); ls[5] += __expf(b.y - mx[5]);
        ls[6] += __expf(b.z - mx[6]); ls[7] += __expf(b.w - mx[7]);
    }
    #pragma unroll
    for (int h = 0; h < 8; ++h)
        #pragma unroll
        for (int o = 16; o > 0; o >>= 1)
            ls[h] += __shfl_xor_sync(0xffffffffu, ls[h], o);
    if (lane == 0)
        #pragma unroll
        for (int h = 0; h < 8; ++h) red[wid][h] = ls[h];
    __syncthreads();
    if (tid < 8) {
        float d = 0.f;
        #pragma unroll
        for (int w = 0; w < 8; ++w) d += red[w][tid];
        if (!(d > 0.f)) d = 1.f;
        g_denv[g * 8 + tid] = d;
    }
}

// ---------------------------------------------------------------------------
__global__ void k_weights(const int* __restrict__ batch,
                          float* __restrict__ w_out,
                          float* __restrict__ ent_out)
{
    int r = blockIdx.x * 256 + threadIdx.x;
    int b = batch[r];
    const float4* lp = reinterpret_cast<const float4*>(g_logits + (size_t)r * 8);
    const float4* mp = reinterpret_cast<const float4*>(g_maxv + b * 8);
    const float4* dp = reinterpret_cast<const float4*>(g_denv + b * 8);
    float4 l0 = lp[0], l1 = lp[1];
    float4 m0 = __ldg(mp), m1 = __ldg(mp + 1);
    float4 d0 = __ldg(dp), d1 = __ldg(dp + 1);

    float w[8];
    w[0] = __expf(l0.x - m0.x) / d0.x;
    w[1] = __expf(l0.y - m0.y) / d0.y;
    w[2] = __expf(l0.z - m0.z) / d0.z;
    w[3] = __expf(l0.w - m0.w) / d0.w;
    w[4] = __expf(l1.x - m1.x) / d1.x;
    w[5] = __expf(l1.y - m1.y) / d1.y;
    w[6] = __expf(l1.z - m1.z) / d1.z;
    w[7] = __expf(l1.w - m1.w) / d1.w;

    float4* op = reinterpret_cast<float4*>(w_out + (size_t)r * 8);
    op[0] = make_float4(w[0], w[1], w[2], w[3]);
    op[1] = make_float4(w[4], w[5], w[6], w[7]);

    float ent = 0.f;
    #pragma unroll
    for (int h = 0; h < 8; ++h) ent += w[h] * logf(w[h] + SM_EPS);
    #pragma unroll
    for (int o = 16; o > 0; o >>= 1)
        ent += __shfl_xor_sync(0xffffffffu, ent, o);
    if ((threadIdx.x & 31) == 0)
        atomicAdd(ent_out, -ent * (1.f / ((float)NG * (float)NHEADS)));
}

// ---------------------------------------------------------------------------
__global__ void k_scatter(const float* __restrict__ x,
                          const float* __restrict__ w,
                          float* __restrict__ gz)
{
    int g = blockIdx.x;
    int d = threadIdx.x;
    int s = g_off[g], e = g_off[g + 1];
    int h = d >> 6;
    float acc = 0.f;
    int r = s;
    for (; r + 4 <= e; r += 4) {
        float x0 = __ldg(x + (size_t)(r + 0) * HID + d);
        float x1 = __ldg(x + (size_t)(r + 1) * HID + d);
        float x2 = __ldg(x + (size_t)(r + 2) * HID + d);
        float x3 = __ldg(x + (size_t)(r + 3) * HID + d);
        float w0 = __ldg(w + (size_t)(r + 0) * 8 + h);
        float w1 = __ldg(w + (size_t)(r + 1) * 8 + h);
        float w2 = __ldg(w + (size_t)(r + 2) * 8 + h);
        float w3 = __ldg(w + (size_t)(r + 3) * 8 + h);
        acc += x0 * w0 + x1 * w1 + x2 * w2 + x3 * w3;
    }
    for (; r < e; ++r)
        acc += __ldg(x + (size_t)r * HID + d) * __ldg(w + (size_t)r * 8 + h);
    gz[(size_t)g * HID + d] = acc;
}

// ---------------------------------------------------------------------------
extern "C" void kernel_launch(void* const* d_in, const int* in_sizes, int n_in,
                              void* d_out, int out_size)
{
    (void)in_sizes; (void)n_in; (void)out_size;
    const float* x     = (const float*)d_in[0];
    const int*   batch = (const int*)  d_in[1];
    const float* gamma = (const float*)d_in[2];
    const float* beta  = (const float*)d_in[3];
    const float* W1    = (const float*)d_in[4];
    const float* b1    = (const float*)d_in[5];
    const float* W2    = (const float*)d_in[6];
    const float* b2    = (const float*)d_in[7];

    float* gz    = (float*)d_out;                    // [G, 512]
    float* w_out = gz + (size_t)NG * HID;            // [N, 8]
    float* ent   = w_out + (size_t)NROWS * NHEADS;   // [1]

    cudaFuncSetAttribute(k_logits_mma, cudaFuncAttributeMaxDynamicSharedMemorySize,
                         SMEM_TOT);

    k_init<<<1, 32>>>(ent);
    k_bounds<<<NROWS / 256, 256>>>(batch);
    k_prepw<<<HID, 256>>>(W1);
    k_logits_mma<<<NROWS / TM, NTHR, SMEM_TOT>>>(x, gamma, beta, b1, W2, b2);
    k_stats<<<NG, 256>>>();
    k_weights<<<NROWS / 256, 256>>>(batch, w_out, ent);
    k_scatter<<<NG, 512>>>(x, w_out, gz);
}

// round 10
// speedup vs baseline: 1.1278x; 1.1278x over previous
#include <cuda_runtime.h>
#include <cuda_bf16.h>
#include <math.h>
#include <stdint.h>

#define NROWS   262144
#define HID     512
#define NHEADS  8
#define NG      1024
#define NHID1   256
#define LN_EPS  1e-5f
#define SM_EPS  1e-8f

// ---- HMMA tiling: 2 CTAs/SM, each 64x256, 8 warps (grid 2x4, warp 32x64) ----
#define TM      64           // rows per CTA
#define TN      256          // full N
#define BK      32           // K per chunk
#define NCH     16           // 512 / 32
#define NTHR    256          // 8 warps

// A smem row stride: 32 bf16 + 8 pad = 40 bf16 = 80 B
#define ARS     80
// B smem row stride: 256 bf16 + 8 pad = 264 bf16 = 528 B
#define BRS     528

// per-buffer byte offsets
#define OFF_AH   0
#define OFF_AL   5120         // 64*80
#define OFF_BH   10240
#define OFF_BL   27136        // +32*528
#define BUF_SZ   44032        // per stage
// tail region
#define OFF_W2   88064        // 256*8 f32 = 8192
#define OFF_B1   96256        // 256 f32 = 1024
#define OFF_MU   97280        // 64 f32 = 256
#define OFF_RS   97536        // 64 f32 = 256
#define OFF_LG   97792        // 64*8 f32 = 2048
#define OFF_GS   99840        // 512 f32 = 2048
#define OFF_BT   101888       // 512 f32 = 2048
#define SMEM_TOT 103936

static __device__ float g_logits[(size_t)NROWS * NHEADS];
static __device__ float g_maxv[NG * NHEADS];
static __device__ float g_denv[NG * NHEADS];
static __device__ int   g_off[NG + 1];
// W1 hi/lo bf16 split, row-major [512(k)][256(n)]
static __device__ __nv_bfloat16 g_Bhi[HID * NHID1];
static __device__ __nv_bfloat16 g_Blo[HID * NHID1];

// ---------------------------------------------------------------------------
__device__ __forceinline__ uint32_t smem_u32(const void* p)
{
    uint32_t a;
    asm("{ .reg .u64 t; cvta.to.shared.u64 t, %1; cvt.u32.u64 %0, t; }"
        : "=r"(a) : "l"(p));
    return a;
}

__device__ __forceinline__ void ldsm4(uint32_t* r, uint32_t addr)
{
    asm volatile("ldmatrix.sync.aligned.m8n8.x4.shared.b16 {%0,%1,%2,%3}, [%4];"
                 : "=r"(r[0]), "=r"(r[1]), "=r"(r[2]), "=r"(r[3]) : "r"(addr));
}

__device__ __forceinline__ void ldsm4t(uint32_t* r, uint32_t addr)
{
    asm volatile("ldmatrix.sync.aligned.m8n8.x4.trans.shared.b16 {%0,%1,%2,%3}, [%4];"
                 : "=r"(r[0]), "=r"(r[1]), "=r"(r[2]), "=r"(r[3]) : "r"(addr));
}

__device__ __forceinline__ void mma16816(float* d, const uint32_t* a, const uint32_t* b)
{
    asm volatile(
        "mma.sync.aligned.m16n8k16.row.col.f32.bf16.bf16.f32 "
        "{%0,%1,%2,%3}, {%4,%5,%6,%7}, {%8,%9}, {%0,%1,%2,%3};"
        : "+f"(d[0]), "+f"(d[1]), "+f"(d[2]), "+f"(d[3])
        : "r"(a[0]), "r"(a[1]), "r"(a[2]), "r"(a[3]), "r"(b[0]), "r"(b[1]));
}

__device__ __forceinline__ void cp16(uint32_t dst, const void* src)
{
    asm volatile("cp.async.cg.shared.global [%0], [%1], 16;"
                 :: "r"(dst), "l"(src) : "memory");
}
#define CP_COMMIT() asm volatile("cp.async.commit_group;" ::: "memory")
#define CP_WAIT0()  asm volatile("cp.async.wait_group 0;" ::: "memory")

__device__ __forceinline__ unsigned pk(__nv_bfloat16 a, __nv_bfloat16 b)
{
    __nv_bfloat162 t = __halves2bfloat162(a, b);
    return *reinterpret_cast<unsigned*>(&t);
}

// transform one float4 of x -> LN -> bf16 hi/lo, store 8B each
__device__ __forceinline__ void xf_store(char* smc, uint32_t base, int row, int kq,
                                         float4 v, float mu, float rs,
                                         float4 gv, float4 bv)
{
    float n0 = (v.x - mu) * rs * gv.x + bv.x;
    float n1 = (v.y - mu) * rs * gv.y + bv.y;
    float n2 = (v.z - mu) * rs * gv.z + bv.z;
    float n3 = (v.w - mu) * rs * gv.w + bv.w;
    __nv_bfloat16 h0 = __float2bfloat16(n0), h1 = __float2bfloat16(n1);
    __nv_bfloat16 h2 = __float2bfloat16(n2), h3 = __float2bfloat16(n3);
    *reinterpret_cast<uint2*>(smc + base + OFF_AH + row * ARS + kq * 2) =
        make_uint2(pk(h0, h1), pk(h2, h3));
    *reinterpret_cast<uint2*>(smc + base + OFF_AL + row * ARS + kq * 2) =
        make_uint2(pk(__float2bfloat16(n0 - __bfloat162float(h0)),
                      __float2bfloat16(n1 - __bfloat162float(h1))),
                   pk(__float2bfloat16(n2 - __bfloat162float(h2)),
                      __float2bfloat16(n3 - __bfloat162float(h3))));
}

// ---------------------------------------------------------------------------
__global__ void k_init(float* __restrict__ ent)
{
    if (threadIdx.x == 0) *ent = 0.f;
}

__global__ void k_bounds(const int* __restrict__ batch)
{
    int i = blockIdx.x * blockDim.x + threadIdx.x;
    if (i >= NROWS) return;
    int cur  = batch[i];
    int prev = (i == 0) ? -1 : batch[i - 1];
    for (int g = prev + 1; g <= cur; ++g) g_off[g] = i;
    if (i == NROWS - 1)
        for (int g = cur + 1; g <= NG; ++g) g_off[g] = NROWS;
}

__global__ void k_prepw(const float* __restrict__ W1)
{
    int i = blockIdx.x * 256 + threadIdx.x;
    float v = W1[i];
    __nv_bfloat16 h = __float2bfloat16(v);
    __nv_bfloat16 l = __float2bfloat16(v - __bfloat162float(h));
    g_Bhi[i] = h;
    g_Blo[i] = l;
}

// ---------------------------------------------------------------------------
// Fused LayerNorm + GEMM1 (bf16 HMMA, 3-product hi/lo split) + SiLU + GEMM2
// 2 CTAs/SM x 8 warps, warp tile 32x64
// ---------------------------------------------------------------------------
__global__ __launch_bounds__(NTHR, 2)
void k_logits_mma(const float* __restrict__ x,
                  const float* __restrict__ gamma,
                  const float* __restrict__ beta,
                  const float* __restrict__ b1,
                  const float* __restrict__ W2,
                  const float* __restrict__ b2)
{
    extern __shared__ char smc[];
    float* smf = reinterpret_cast<float*>(smc);
    const uint32_t sb = smem_u32(smc);

    const int tid  = threadIdx.x;
    const int wid  = tid >> 5;
    const int lane = tid & 31;
    const int m_base = blockIdx.x * TM;

    // tail-region fills
    for (int i = tid; i < 2048; i += NTHR) smf[OFF_W2 / 4 + i] = W2[i];
    if (tid < 256) smf[OFF_B1 / 4 + tid] = b1[tid];
    for (int i = tid; i < HID; i += NTHR) {
        smf[OFF_GS / 4 + i] = gamma[i];
        smf[OFF_BT / 4 + i] = beta[i];
    }
    for (int i = tid; i < TM * NHEADS; i += NTHR)
        smf[OFF_LG / 4 + i] = b2[i & 7];

    // ---- LayerNorm stats: 4 threads per row ----
    {
        int row = tid >> 2, part = tid & 3;
        const float4* xr = reinterpret_cast<const float4*>(
            x + (size_t)(m_base + row) * HID) + part * 32;
        float s = 0.f, s2 = 0.f;
        #pragma unroll 8
        for (int i = 0; i < 32; ++i) {
            float4 v = __ldg(xr + i);
            s  += v.x + v.y + v.z + v.w;
            s2 += v.x * v.x + v.y * v.y + v.z * v.z + v.w * v.w;
        }
        s  += __shfl_xor_sync(0xffffffffu, s, 1);
        s  += __shfl_xor_sync(0xffffffffu, s, 2);
        s2 += __shfl_xor_sync(0xffffffffu, s2, 1);
        s2 += __shfl_xor_sync(0xffffffffu, s2, 2);
        if (!part) {
            float m = s * (1.f / HID);
            float v = s2 * (1.f / HID) - m * m;
            smf[OFF_MU / 4 + row] = m;
            smf[OFF_RS / 4 + row] = rsqrtf(v + LN_EPS);
        }
    }
    __syncthreads();

    // per-thread A geometry: 2 slots, rows tid>>3 + {0,32}, same kq
    const int a_kq = (tid & 7) * 4;
    int   a_row[2];
    float a_mu[2], a_rs[2];
    const float* xp[2];
    #pragma unroll
    for (int s = 0; s < 2; ++s) {
        a_row[s] = (tid >> 3) + s * 32;
        a_mu[s]  = smf[OFF_MU / 4 + a_row[s]];
        a_rs[s]  = smf[OFF_RS / 4 + a_row[s]];
        xp[s]    = x + (size_t)(m_base + a_row[s]) * HID + a_kq;
    }

    // B copy geometry: 4 float4 slots per matrix
    int b_r[4], b_c[4];
    #pragma unroll
    for (int s = 0; s < 4; ++s) {
        int j = tid + s * 256;
        b_r[s] = j >> 5;
        b_c[s] = (j & 31) * 16;
    }

    // warp MMA geometry: grid 2(m) x 4(n), warp tile 32x64
    const int wm = (wid >> 2) * 32;
    const int wn = (wid & 3) * 64;
    const uint32_t a_lds = (uint32_t)((wm + (lane & 15)) * ARS + (lane >> 4) * 16);
    const uint32_t b_lds = (uint32_t)((lane & 15) * BRS + (wn + (lane >> 4) * 8) * 2);

    float acc[2][8][4];
    #pragma unroll
    for (int mt = 0; mt < 2; ++mt)
        #pragma unroll
        for (int nt = 0; nt < 8; ++nt)
            #pragma unroll
            for (int e = 0; e < 4; ++e) acc[mt][nt][e] = 0.f;

    float4 xr[2];

    // ---- prologue: fill buffer 0 (chunk 0) ----
    {
        #pragma unroll
        for (int s = 0; s < 4; ++s) {
            cp16(sb + OFF_BH + b_r[s] * BRS + b_c[s],
                 (const char*)g_Bhi + b_r[s] * 512 + b_c[s]);
            cp16(sb + OFF_BL + b_r[s] * BRS + b_c[s],
                 (const char*)g_Blo + b_r[s] * 512 + b_c[s]);
        }
        CP_COMMIT();
        #pragma unroll
        for (int s = 0; s < 2; ++s)
            xr[s] = __ldg(reinterpret_cast<const float4*>(xp[s]));
        const float4 gv = *reinterpret_cast<const float4*>(&smf[OFF_GS / 4 + a_kq]);
        const float4 bv = *reinterpret_cast<const float4*>(&smf[OFF_BT / 4 + a_kq]);
        #pragma unroll
        for (int s = 0; s < 2; ++s)
            xf_store(smc, 0, a_row[s], a_kq, xr[s], a_mu[s], a_rs[s], gv, bv);
        CP_WAIT0();
    }
    __syncthreads();

    // ---- mainloop ----
    for (int t = 0; t < NCH; ++t) {
        const uint32_t bufc = (uint32_t)((t & 1) * BUF_SZ);
        const uint32_t bufn = (uint32_t)(((t + 1) & 1) * BUF_SZ);
        const bool more = (t < NCH - 1);

        if (more) {
            const char* gh = (const char*)g_Bhi + (size_t)(t + 1) * 32 * 512;
            const char* gl = (const char*)g_Blo + (size_t)(t + 1) * 32 * 512;
            #pragma unroll
            for (int s = 0; s < 4; ++s) {
                cp16(sb + bufn + OFF_BH + b_r[s] * BRS + b_c[s], gh + b_r[s] * 512 + b_c[s]);
                cp16(sb + bufn + OFF_BL + b_r[s] * BRS + b_c[s], gl + b_r[s] * 512 + b_c[s]);
            }
            CP_COMMIT();
            #pragma unroll
            for (int s = 0; s < 2; ++s)
                xr[s] = __ldg(reinterpret_cast<const float4*>(xp[s] + (t + 1) * BK));
        }

        // MMA ks = 0
        {
            uint32_t ah[2][4], al[2][4];
            #pragma unroll
            for (int mt = 0; mt < 2; ++mt) {
                uint32_t ao = sb + bufc + a_lds + (uint32_t)(mt * 16 * ARS);
                ldsm4(ah[mt], ao + OFF_AH);
                ldsm4(al[mt], ao + OFF_AL);
            }
            #pragma unroll
            for (int np = 0; np < 4; ++np) {
                uint32_t bh[4], bl[4];
                uint32_t bo = sb + bufc + b_lds + (uint32_t)(np * 32);
                ldsm4t(bh, bo + OFF_BH);
                ldsm4t(bl, bo + OFF_BL);
                #pragma unroll
                for (int mt = 0; mt < 2; ++mt) {
                    mma16816(acc[mt][2 * np],     ah[mt], bh);
                    mma16816(acc[mt][2 * np],     ah[mt], bl);
                    mma16816(acc[mt][2 * np],     al[mt], bh);
                    mma16816(acc[mt][2 * np + 1], ah[mt], bh + 2);
                    mma16816(acc[mt][2 * np + 1], ah[mt], bl + 2);
                    mma16816(acc[mt][2 * np + 1], al[mt], bh + 2);
                }
            }
        }

        // transform + store A(t+1) (overlaps tensor-pipe drain of ks=0)
        if (more) {
            const int kb = (t + 1) * BK;
            const float4 gv = *reinterpret_cast<const float4*>(&smf[OFF_GS / 4 + kb + a_kq]);
            const float4 bv = *reinterpret_cast<const float4*>(&smf[OFF_BT / 4 + kb + a_kq]);
            #pragma unroll
            for (int s = 0; s < 2; ++s)
                xf_store(smc, bufn, a_row[s], a_kq, xr[s], a_mu[s], a_rs[s], gv, bv);
        }

        // MMA ks = 1
        {
            uint32_t ah[2][4], al[2][4];
            #pragma unroll
            for (int mt = 0; mt < 2; ++mt) {
                uint32_t ao = sb + bufc + a_lds + (uint32_t)(mt * 16 * ARS + 32);
                ldsm4(ah[mt], ao + OFF_AH);
                ldsm4(al[mt], ao + OFF_AL);
            }
            #pragma unroll
            for (int np = 0; np < 4; ++np) {
                uint32_t bh[4], bl[4];
                uint32_t bo = sb + bufc + b_lds + (uint32_t)(16 * BRS + np * 32);
                ldsm4t(bh, bo + OFF_BH);
                ldsm4t(bl, bo + OFF_BL);
                #pragma unroll
                for (int mt = 0; mt < 2; ++mt) {
                    mma16816(acc[mt][2 * np],     ah[mt], bh);
                    mma16816(acc[mt][2 * np],     ah[mt], bl);
                    mma16816(acc[mt][2 * np],     al[mt], bh);
                    mma16816(acc[mt][2 * np + 1], ah[mt], bh + 2);
                    mma16816(acc[mt][2 * np + 1], ah[mt], bl + 2);
                    mma16816(acc[mt][2 * np + 1], al[mt], bh + 2);
                }
            }
        }

        if (more) CP_WAIT0();
        __syncthreads();
    }

    // ---- epilogue: SiLU + GEMM2 (h @ W2), accumulate logits in smem ----
    const int g = lane >> 2, q = lane & 3;
    float pacc[4][8];
    #pragma unroll
    for (int r = 0; r < 4; ++r)
        #pragma unroll
        for (int h = 0; h < 8; ++h) pacc[r][h] = 0.f;

    #pragma unroll
    for (int nt = 0; nt < 8; ++nt) {
        const int c0 = wn + nt * 8 + q * 2;
        const float4 w0a = *reinterpret_cast<const float4*>(&smf[OFF_W2 / 4 + c0 * 8]);
        const float4 w0b = *reinterpret_cast<const float4*>(&smf[OFF_W2 / 4 + c0 * 8 + 4]);
        const float4 w1a = *reinterpret_cast<const float4*>(&smf[OFF_W2 / 4 + (c0 + 1) * 8]);
        const float4 w1b = *reinterpret_cast<const float4*>(&smf[OFF_W2 / 4 + (c0 + 1) * 8 + 4]);
        const float b1c0 = smf[OFF_B1 / 4 + c0];
        const float b1c1 = smf[OFF_B1 / 4 + c0 + 1];
        #pragma unroll
        for (int mt = 0; mt < 2; ++mt) {
            #pragma unroll
            for (int e = 0; e < 4; ++e) {
                float hv = acc[mt][nt][e] + ((e & 1) ? b1c1 : b1c0);
                float sv = hv / (1.f + __expf(-hv));
                const int r = mt * 2 + (e >> 1);
                const float4 wa = (e & 1) ? w1a : w0a;
                const float4 wb = (e & 1) ? w1b : w0b;
                pacc[r][0] += sv * wa.x; pacc[r][1] += sv * wa.y;
                pacc[r][2] += sv * wa.z; pacc[r][3] += sv * wa.w;
                pacc[r][4] += sv * wb.x; pacc[r][5] += sv * wb.y;
                pacc[r][6] += sv * wb.z; pacc[r][7] += sv * wb.w;
            }
        }
    }
    #pragma unroll
    for (int r = 0; r < 4; ++r)
        #pragma unroll
        for (int h = 0; h < 8; ++h) {
            pacc[r][h] += __shfl_xor_sync(0xffffffffu, pacc[r][h], 1);
            pacc[r][h] += __shfl_xor_sync(0xffffffffu, pacc[r][h], 2);
        }
    if (q == 0) {
        #pragma unroll
        for (int r = 0; r < 4; ++r) {
            const int row = wm + (r >> 1) * 16 + (r & 1) * 8 + g;
            #pragma unroll
            for (int h = 0; h < 8; ++h)
                atomicAdd(&smf[OFF_LG / 4 + row * 8 + h], pacc[r][h]);
        }
    }
    __syncthreads();

    if (tid < TM) {
        const float4* src = reinterpret_cast<const float4*>(&smf[OFF_LG / 4 + tid * 8]);
        float4* dst = reinterpret_cast<float4*>(g_logits + (size_t)(m_base + tid) * 8);
        dst[0] = src[0];
        dst[1] = src[1];
    }
}

// ---------------------------------------------------------------------------
__global__ void k_stats()
{
    int g = blockIdx.x;
    int s = g_off[g], e = g_off[g + 1];
    int tid = threadIdx.x, lane = tid & 31, wid = tid >> 5;
    __shared__ float red[8][8];
    __shared__ float smax[8];

    float lm[8];
    #pragma unroll
    for (int h = 0; h < 8; ++h) lm[h] = -INFINITY;
    for (int r = s + tid; r < e; r += 256) {
        const float4* lp = reinterpret_cast<const float4*>(g_logits + (size_t)r * 8);
        float4 a = lp[0], b = lp[1];
        lm[0] = fmaxf(lm[0], a.x); lm[1] = fmaxf(lm[1], a.y);
        lm[2] = fmaxf(lm[2], a.z); lm[3] = fmaxf(lm[3], a.w);
        lm[4] = fmaxf(lm[4], b.x); lm[5] = fmaxf(lm[5], b.y);
        lm[6] = fmaxf(lm[6], b.z); lm[7] = fmaxf(lm[7], b.w);
    }
    #pragma unroll
    for (int h = 0; h < 8; ++h)
        #pragma unroll
        for (int o = 16; o > 0; o >>= 1)
            lm[h] = fmaxf(lm[h], __shfl_xor_sync(0xffffffffu, lm[h], o));
    if (lane == 0)
        #pragma unroll
        for (int h = 0; h < 8; ++h) red[wid][h] = lm[h];
    __syncthreads();
    if (tid < 8) {
        float m = red[0][tid];
        #pragma unroll
        for (int w = 1; w < 8; ++w) m = fmaxf(m, red[w][tid]);
        if (!(m >= -3.0e38f)) m = 0.f;
        smax[tid] = m;
        g_maxv[g * 8 + tid] = m;
    }
    __syncthreads();

    float mx[8], ls[8];
    #pragma unroll
    for (int h = 0; h < 8; ++h) { mx[h] = smax[h]; ls[h] = 0.f; }
    for (int r = s + tid; r < e; r += 256) {
        const float4* lp = reinterpret_cast<const float4*>(g_logits + (size_t)r * 8);
        float4 a = lp[0], b = lp[1];
        ls[0] += __expf(a.x - mx[0]); ls[1] += __expf(a.y - mx[1]);
        ls[2] += __expf(a.z - mx[2]); ls[3] += __expf(a.w - mx[3]);
        ls[4] += __expf(b.x - mx[4]); ls[5] += __expf(b.y - mx[5]);
        ls[6] += __expf(b.z - mx[6]); ls[7] += __expf(b.w - mx[7]);
    }
    #pragma unroll
    for (int h = 0; h < 8; ++h)
        #pragma unroll
        for (int o = 16; o > 0; o >>= 1)
            ls[h] += __shfl_xor_sync(0xffffffffu, ls[h], o);
    if (lane == 0)
        #pragma unroll
        for (int h = 0; h < 8; ++h) red[wid][h] = ls[h];
    __syncthreads();
    if (tid < 8) {
        float d = 0.f;
        #pragma unroll
        for (int w = 0; w < 8; ++w) d += red[w][tid];
        if (!(d > 0.f)) d = 1.f;
        g_denv[g * 8 + tid] = d;
    }
}

// ---------------------------------------------------------------------------
__global__ void k_weights(const int* __restrict__ batch,
                          float* __restrict__ w_out,
                          float* __restrict__ ent_out)
{
    int r = blockIdx.x * 256 + threadIdx.x;
    int b = batch[r];
    const float4* lp = reinterpret_cast<const float4*>(g_logits + (size_t)r * 8);
    const float4* mp = reinterpret_cast<const float4*>(g_maxv + b * 8);
    const float4* dp = reinterpret_cast<const float4*>(g_denv + b * 8);
    float4 l0 = lp[0], l1 = lp[1];
    float4 m0 = __ldg(mp), m1 = __ldg(mp + 1);
    float4 d0 = __ldg(dp), d1 = __ldg(dp + 1);

    float w[8];
    w[0] = __expf(l0.x - m0.x) / d0.x;
    w[1] = __expf(l0.y - m0.y) / d0.y;
    w[2] = __expf(l0.z - m0.z) / d0.z;
    w[3] = __expf(l0.w - m0.w) / d0.w;
    w[4] = __expf(l1.x - m1.x) / d1.x;
    w[5] = __expf(l1.y - m1.y) / d1.y;
    w[6] = __expf(l1.z - m1.z) / d1.z;
    w[7] = __expf(l1.w - m1.w) / d1.w;

    float4* op = reinterpret_cast<float4*>(w_out + (size_t)r * 8);
    op[0] = make_float4(w[0], w[1], w[2], w[3]);
    op[1] = make_float4(w[4], w[5], w[6], w[7]);

    float ent = 0.f;
    #pragma unroll
    for (int h = 0; h < 8; ++h) ent += w[h] * logf(w[h] + SM_EPS);
    #pragma unroll
    for (int o = 16; o > 0; o >>= 1)
        ent += __shfl_xor_sync(0xffffffffu, ent, o);
    if ((threadIdx.x & 31) == 0)
        atomicAdd(ent_out, -ent * (1.f / ((float)NG * (float)NHEADS)));
}

// ---------------------------------------------------------------------------
__global__ void k_scatter(const float* __restrict__ x,
                          const float* __restrict__ w,
                          float* __restrict__ gz)
{
    int g = blockIdx.x;
    int d = threadIdx.x;
    int s = g_off[g], e = g_off[g + 1];
    int h = d >> 6;
    float acc = 0.f;
    int r = s;
    for (; r + 4 <= e; r += 4) {
        float x0 = __ldg(x + (size_t)(r + 0) * HID + d);
        float x1 = __ldg(x + (size_t)(r + 1) * HID + d);
        float x2 = __ldg(x + (size_t)(r + 2) * HID + d);
        float x3 = __ldg(x + (size_t)(r + 3) * HID + d);
        float w0 = __ldg(w + (size_t)(r + 0) * 8 + h);
        float w1 = __ldg(w + (size_t)(r + 1) * 8 + h);
        float w2 = __ldg(w + (size_t)(r + 2) * 8 + h);
        float w3 = __ldg(w + (size_t)(r + 3) * 8 + h);
        acc += x0 * w0 + x1 * w1 + x2 * w2 + x3 * w3;
    }
    for (; r < e; ++r)
        acc += __ldg(x + (size_t)r * HID + d) * __ldg(w + (size_t)r * 8 + h);
    gz[(size_t)g * HID + d] = acc;
}

// ---------------------------------------------------------------------------
extern "C" void kernel_launch(void* const* d_in, const int* in_sizes, int n_in,
                              void* d_out, int out_size)
{
    (void)in_sizes; (void)n_in; (void)out_size;
    const float* x     = (const float*)d_in[0];
    const int*   batch = (const int*)  d_in[1];
    const float* gamma = (const float*)d_in[2];
    const float* beta  = (const float*)d_in[3];
    const float* W1    = (const float*)d_in[4];
    const float* b1    = (const float*)d_in[5];
    const float* W2    = (const float*)d_in[6];
    const float* b2    = (const float*)d_in[7];

    float* gz    = (float*)d_out;                    // [G, 512]
    float* w_out = gz + (size_t)NG * HID;            // [N, 8]
    float* ent   = w_out + (size_t)NROWS * NHEADS;   // [1]

    cudaFuncSetAttribute(k_logits_mma, cudaFuncAttributeMaxDynamicSharedMemorySize,
                         SMEM_TOT);

    k_init<<<1, 32>>>(ent);
    k_bounds<<<NROWS / 256, 256>>>(batch);
    k_prepw<<<HID, 256>>>(W1);
    k_logits_mma<<<NROWS / TM, NTHR, SMEM_TOT>>>(x, gamma, beta, b1, W2, b2);
    k_stats<<<NG, 256>>>();
    k_weights<<<NROWS / 256, 256>>>(batch, w_out, ent);
    k_scatter<<<NG, 512>>>(x, w_out, gz);
}

// round 11
// speedup vs baseline: 1.4390x; 1.2760x over previous
#include <cuda_runtime.h>
#include <cuda_fp16.h>
#include <math.h>
#include <stdint.h>

#define NROWS   262144
#define HID     512
#define NHEADS  8
#define NG      1024
#define NHID1   256
#define LN_EPS  1e-5f
#define SM_EPS  1e-8f

// ---- HMMA tiling: 2 CTAs/SM, each 64x256, 8 warps (grid 2x4, warp 32x64) ----
// fp16 2-product split: x = xh + xl (fp16), W1 single fp16.
#define TM      64           // rows per CTA
#define TN      256          // full N
#define BK      32           // K per chunk
#define NCH     16           // 512 / 32
#define NTHR    256          // 8 warps

// A smem row stride: 32 fp16 + 8 pad = 40 fp16 = 80 B
#define ARS     80
// B smem row stride: 256 fp16 + 8 pad = 264 fp16 = 528 B
#define BRS     528

// per-buffer byte offsets
#define OFF_AH   0
#define OFF_AL   5120         // 64*80
#define OFF_BH   10240
#define BUF_SZ   27136        // 10240 + 32*528
// tail region
#define OFF_W2   54272        // 256*8 f32 = 8192
#define OFF_B1   62464        // 256 f32 = 1024
#define OFF_MU   63488        // 64 f32 = 256
#define OFF_RS   63744        // 64 f32 = 256
#define OFF_LG   64000        // 64*8 f32 = 2048
#define OFF_GS   66048        // 512 f32 = 2048
#define OFF_BT   68096        // 512 f32 = 2048
#define SMEM_TOT 70144

static __device__ float g_logits[(size_t)NROWS * NHEADS];
static __device__ float g_maxv[NG * NHEADS];
static __device__ float g_denv[NG * NHEADS];
static __device__ int   g_off[NG + 1];
// W1 fp16, row-major [512(k)][256(n)]
static __device__ __half g_Bh[HID * NHID1];

// ---------------------------------------------------------------------------
__device__ __forceinline__ uint32_t smem_u32(const void* p)
{
    uint32_t a;
    asm("{ .reg .u64 t; cvta.to.shared.u64 t, %1; cvt.u32.u64 %0, t; }"
        : "=r"(a) : "l"(p));
    return a;
}

__device__ __forceinline__ void ldsm4(uint32_t* r, uint32_t addr)
{
    asm volatile("ldmatrix.sync.aligned.m8n8.x4.shared.b16 {%0,%1,%2,%3}, [%4];"
                 : "=r"(r[0]), "=r"(r[1]), "=r"(r[2]), "=r"(r[3]) : "r"(addr));
}

__device__ __forceinline__ void ldsm4t(uint32_t* r, uint32_t addr)
{
    asm volatile("ldmatrix.sync.aligned.m8n8.x4.trans.shared.b16 {%0,%1,%2,%3}, [%4];"
                 : "=r"(r[0]), "=r"(r[1]), "=r"(r[2]), "=r"(r[3]) : "r"(addr));
}

__device__ __forceinline__ void mma16816(float* d, const uint32_t* a, const uint32_t* b)
{
    asm volatile(
        "mma.sync.aligned.m16n8k16.row.col.f32.f16.f16.f32 "
        "{%0,%1,%2,%3}, {%4,%5,%6,%7}, {%8,%9}, {%0,%1,%2,%3};"
        : "+f"(d[0]), "+f"(d[1]), "+f"(d[2]), "+f"(d[3])
        : "r"(a[0]), "r"(a[1]), "r"(a[2]), "r"(a[3]), "r"(b[0]), "r"(b[1]));
}

__device__ __forceinline__ void cp16(uint32_t dst, const void* src)
{
    asm volatile("cp.async.cg.shared.global [%0], [%1], 16;"
                 :: "r"(dst), "l"(src) : "memory");
}
#define CP_COMMIT() asm volatile("cp.async.commit_group;" ::: "memory")
#define CP_WAIT0()  asm volatile("cp.async.wait_group 0;" ::: "memory")

__device__ __forceinline__ unsigned pk(__half a, __half b)
{
    __half2 t = __halves2half2(a, b);
    return *reinterpret_cast<unsigned*>(&t);
}

// transform one float4 of x -> LN -> fp16 hi/lo, store 8B each
__device__ __forceinline__ void xf_store(char* smc, uint32_t base, int row, int kq,
                                         float4 v, float mu, float rs,
                                         float4 gv, float4 bv)
{
    float n0 = (v.x - mu) * rs * gv.x + bv.x;
    float n1 = (v.y - mu) * rs * gv.y + bv.y;
    float n2 = (v.z - mu) * rs * gv.z + bv.z;
    float n3 = (v.w - mu) * rs * gv.w + bv.w;
    __half h0 = __float2half(n0), h1 = __float2half(n1);
    __half h2 = __float2half(n2), h3 = __float2half(n3);
    *reinterpret_cast<uint2*>(smc + base + OFF_AH + row * ARS + kq * 2) =
        make_uint2(pk(h0, h1), pk(h2, h3));
    *reinterpret_cast<uint2*>(smc + base + OFF_AL + row * ARS + kq * 2) =
        make_uint2(pk(__float2half(n0 - __half2float(h0)),
                      __float2half(n1 - __half2float(h1))),
                   pk(__float2half(n2 - __half2float(h2)),
                      __float2half(n3 - __half2float(h3))));
}

// ---------------------------------------------------------------------------
__global__ void k_init(float* __restrict__ ent)
{
    if (threadIdx.x == 0) *ent = 0.f;
}

__global__ void k_bounds(const int* __restrict__ batch)
{
    int i = blockIdx.x * blockDim.x + threadIdx.x;
    if (i >= NROWS) return;
    int cur  = batch[i];
    int prev = (i == 0) ? -1 : batch[i - 1];
    for (int g = prev + 1; g <= cur; ++g) g_off[g] = i;
    if (i == NROWS - 1)
        for (int g = cur + 1; g <= NG; ++g) g_off[g] = NROWS;
}

__global__ void k_prepw(const float* __restrict__ W1)
{
    int i = blockIdx.x * 256 + threadIdx.x;
    g_Bh[i] = __float2half(W1[i]);
}

// ---------------------------------------------------------------------------
// Fused LayerNorm + GEMM1 (fp16 HMMA, 2-product hi/lo split) + SiLU + GEMM2
// 2 CTAs/SM x 8 warps, warp tile 32x64
// ---------------------------------------------------------------------------
__global__ __launch_bounds__(NTHR, 2)
void k_logits_mma(const float* __restrict__ x,
                  const float* __restrict__ gamma,
                  const float* __restrict__ beta,
                  const float* __restrict__ b1,
                  const float* __restrict__ W2,
                  const float* __restrict__ b2)
{
    extern __shared__ char smc[];
    float* smf = reinterpret_cast<float*>(smc);
    const uint32_t sb = smem_u32(smc);

    const int tid  = threadIdx.x;
    const int wid  = tid >> 5;
    const int lane = tid & 31;
    const int m_base = blockIdx.x * TM;

    // tail-region fills
    for (int i = tid; i < 2048; i += NTHR) smf[OFF_W2 / 4 + i] = W2[i];
    if (tid < 256) smf[OFF_B1 / 4 + tid] = b1[tid];
    for (int i = tid; i < HID; i += NTHR) {
        smf[OFF_GS / 4 + i] = gamma[i];
        smf[OFF_BT / 4 + i] = beta[i];
    }
    for (int i = tid; i < TM * NHEADS; i += NTHR)
        smf[OFF_LG / 4 + i] = b2[i & 7];

    // ---- LayerNorm stats: 4 threads per row ----
    {
        int row = tid >> 2, part = tid & 3;
        const float4* xr = reinterpret_cast<const float4*>(
            x + (size_t)(m_base + row) * HID) + part * 32;
        float s = 0.f, s2 = 0.f;
        #pragma unroll 8
        for (int i = 0; i < 32; ++i) {
            float4 v = __ldg(xr + i);
            s  += v.x + v.y + v.z + v.w;
            s2 += v.x * v.x + v.y * v.y + v.z * v.z + v.w * v.w;
        }
        s  += __shfl_xor_sync(0xffffffffu, s, 1);
        s  += __shfl_xor_sync(0xffffffffu, s, 2);
        s2 += __shfl_xor_sync(0xffffffffu, s2, 1);
        s2 += __shfl_xor_sync(0xffffffffu, s2, 2);
        if (!part) {
            float m = s * (1.f / HID);
            float v = s2 * (1.f / HID) - m * m;
            smf[OFF_MU / 4 + row] = m;
            smf[OFF_RS / 4 + row] = rsqrtf(v + LN_EPS);
        }
    }
    __syncthreads();

    // per-thread A geometry: 2 slots, rows tid>>3 + {0,32}, same kq
    const int a_kq = (tid & 7) * 4;
    int   a_row[2];
    float a_mu[2], a_rs[2];
    const float* xp[2];
    #pragma unroll
    for (int s = 0; s < 2; ++s) {
        a_row[s] = (tid >> 3) + s * 32;
        a_mu[s]  = smf[OFF_MU / 4 + a_row[s]];
        a_rs[s]  = smf[OFF_RS / 4 + a_row[s]];
        xp[s]    = x + (size_t)(m_base + a_row[s]) * HID + a_kq;
    }

    // B copy geometry: 4 float4 slots (32 rows x 512 B = 1024 float4)
    int b_r[4], b_c[4];
    #pragma unroll
    for (int s = 0; s < 4; ++s) {
        int j = tid + s * 256;
        b_r[s] = j >> 5;
        b_c[s] = (j & 31) * 16;
    }

    // warp MMA geometry: grid 2(m) x 4(n), warp tile 32x64
    const int wm = (wid >> 2) * 32;
    const int wn = (wid & 3) * 64;
    const uint32_t a_lds = (uint32_t)((wm + (lane & 15)) * ARS + (lane >> 4) * 16);
    const uint32_t b_lds = (uint32_t)((lane & 15) * BRS + (wn + (lane >> 4) * 8) * 2);

    float acc[2][8][4];
    #pragma unroll
    for (int mt = 0; mt < 2; ++mt)
        #pragma unroll
        for (int nt = 0; nt < 8; ++nt)
            #pragma unroll
            for (int e = 0; e < 4; ++e) acc[mt][nt][e] = 0.f;

    float4 xr[2];

    // ---- prologue: fill buffer 0 (chunk 0) ----
    {
        #pragma unroll
        for (int s = 0; s < 4; ++s)
            cp16(sb + OFF_BH + b_r[s] * BRS + b_c[s],
                 (const char*)g_Bh + b_r[s] * 512 + b_c[s]);
        CP_COMMIT();
        #pragma unroll
        for (int s = 0; s < 2; ++s)
            xr[s] = __ldg(reinterpret_cast<const float4*>(xp[s]));
        const float4 gv = *reinterpret_cast<const float4*>(&smf[OFF_GS / 4 + a_kq]);
        const float4 bv = *reinterpret_cast<const float4*>(&smf[OFF_BT / 4 + a_kq]);
        #pragma unroll
        for (int s = 0; s < 2; ++s)
            xf_store(smc, 0, a_row[s], a_kq, xr[s], a_mu[s], a_rs[s], gv, bv);
        CP_WAIT0();
    }
    __syncthreads();

    // ---- mainloop ----
    for (int t = 0; t < NCH; ++t) {
        const uint32_t bufc = (uint32_t)((t & 1) * BUF_SZ);
        const uint32_t bufn = (uint32_t)(((t + 1) & 1) * BUF_SZ);
        const bool more = (t < NCH - 1);

        if (more) {
            const char* gh = (const char*)g_Bh + (size_t)(t + 1) * 32 * 512;
            #pragma unroll
            for (int s = 0; s < 4; ++s)
                cp16(sb + bufn + OFF_BH + b_r[s] * BRS + b_c[s], gh + b_r[s] * 512 + b_c[s]);
            CP_COMMIT();
            #pragma unroll
            for (int s = 0; s < 2; ++s)
                xr[s] = __ldg(reinterpret_cast<const float4*>(xp[s] + (t + 1) * BK));
        }

        // MMA ks = 0
        {
            uint32_t ah[2][4], al[2][4];
            #pragma unroll
            for (int mt = 0; mt < 2; ++mt) {
                uint32_t ao = sb + bufc + a_lds + (uint32_t)(mt * 16 * ARS);
                ldsm4(ah[mt], ao + OFF_AH);
                ldsm4(al[mt], ao + OFF_AL);
            }
            #pragma unroll
            for (int np = 0; np < 4; ++np) {
                uint32_t bh[4];
                uint32_t bo = sb + bufc + b_lds + (uint32_t)(np * 32);
                ldsm4t(bh, bo + OFF_BH);
                #pragma unroll
                for (int mt = 0; mt < 2; ++mt) {
                    mma16816(acc[mt][2 * np],     ah[mt], bh);
                    mma16816(acc[mt][2 * np],     al[mt], bh);
                    mma16816(acc[mt][2 * np + 1], ah[mt], bh + 2);
                    mma16816(acc[mt][2 * np + 1], al[mt], bh + 2);
                }
            }
        }

        // transform + store A(t+1) (overlaps tensor-pipe drain of ks=0)
        if (more) {
            const int kb = (t + 1) * BK;
            const float4 gv = *reinterpret_cast<const float4*>(&smf[OFF_GS / 4 + kb + a_kq]);
            const float4 bv = *reinterpret_cast<const float4*>(&smf[OFF_BT / 4 + kb + a_kq]);
            #pragma unroll
            for (int s = 0; s < 2; ++s)
                xf_store(smc, bufn, a_row[s], a_kq, xr[s], a_mu[s], a_rs[s], gv, bv);
        }

        // MMA ks = 1
        {
            uint32_t ah[2][4], al[2][4];
            #pragma unroll
            for (int mt = 0; mt < 2; ++mt) {
                uint32_t ao = sb + bufc + a_lds + (uint32_t)(mt * 16 * ARS + 32);
                ldsm4(ah[mt], ao + OFF_AH);
                ldsm4(al[mt], ao + OFF_AL);
            }
            #pragma unroll
            for (int np = 0; np < 4; ++np) {
                uint32_t bh[4];
                uint32_t bo = sb + bufc + b_lds + (uint32_t)(16 * BRS + np * 32);
                ldsm4t(bh, bo + OFF_BH);
                #pragma unroll
                for (int mt = 0; mt < 2; ++mt) {
                    mma16816(acc[mt][2 * np],     ah[mt], bh);
                    mma16816(acc[mt][2 * np],     al[mt], bh);
                    mma16816(acc[mt][2 * np + 1], ah[mt], bh + 2);
                    mma16816(acc[mt][2 * np + 1], al[mt], bh + 2);
                }
            }
        }

        if (more) CP_WAIT0();
        __syncthreads();
    }

    // ---- epilogue: SiLU + GEMM2 (h @ W2), accumulate logits in smem ----
    const int g = lane >> 2, q = lane & 3;
    float pacc[4][8];
    #pragma unroll
    for (int r = 0; r < 4; ++r)
        #pragma unroll
        for (int h = 0; h < 8; ++h) pacc[r][h] = 0.f;

    #pragma unroll
    for (int nt = 0; nt < 8; ++nt) {
        const int c0 = wn + nt * 8 + q * 2;
        const float4 w0a = *reinterpret_cast<const float4*>(&smf[OFF_W2 / 4 + c0 * 8]);
        const float4 w0b = *reinterpret_cast<const float4*>(&smf[OFF_W2 / 4 + c0 * 8 + 4]);
        const float4 w1a = *reinterpret_cast<const float4*>(&smf[OFF_W2 / 4 + (c0 + 1) * 8]);
        const float4 w1b = *reinterpret_cast<const float4*>(&smf[OFF_W2 / 4 + (c0 + 1) * 8 + 4]);
        const float b1c0 = smf[OFF_B1 / 4 + c0];
        const float b1c1 = smf[OFF_B1 / 4 + c0 + 1];
        #pragma unroll
        for (int mt = 0; mt < 2; ++mt) {
            #pragma unroll
            for (int e = 0; e < 4; ++e) {
                float hv = acc[mt][nt][e] + ((e & 1) ? b1c1 : b1c0);
                float sv = hv / (1.f + __expf(-hv));
                const int r = mt * 2 + (e >> 1);
                const float4 wa = (e & 1) ? w1a : w0a;
                const float4 wb = (e & 1) ? w1b : w0b;
                pacc[r][0] += sv * wa.x; pacc[r][1] += sv * wa.y;
                pacc[r][2] += sv * wa.z; pacc[r][3] += sv * wa.w;
                pacc[r][4] += sv * wb.x; pacc[r][5] += sv * wb.y;
                pacc[r][6] += sv * wb.z; pacc[r][7] += sv * wb.w;
            }
        }
    }
    #pragma unroll
    for (int r = 0; r < 4; ++r)
        #pragma unroll
        for (int h = 0; h < 8; ++h) {
            pacc[r][h] += __shfl_xor_sync(0xffffffffu, pacc[r][h], 1);
            pacc[r][h] += __shfl_xor_sync(0xffffffffu, pacc[r][h], 2);
        }
    if (q == 0) {
        #pragma unroll
        for (int r = 0; r < 4; ++r) {
            const int row = wm + (r >> 1) * 16 + (r & 1) * 8 + g;
            #pragma unroll
            for (int h = 0; h < 8; ++h)
                atomicAdd(&smf[OFF_LG / 4 + row * 8 + h], pacc[r][h]);
        }
    }
    __syncthreads();

    if (tid < TM) {
        const float4* src = reinterpret_cast<const float4*>(&smf[OFF_LG / 4 + tid * 8]);
        float4* dst = reinterpret_cast<float4*>(g_logits + (size_t)(m_base + tid) * 8);
        dst[0] = src[0];
        dst[1] = src[1];
    }
}

// ---------------------------------------------------------------------------
__global__ void k_stats()
{
    int g = blockIdx.x;
    int s = g_off[g], e = g_off[g + 1];
    int tid = threadIdx.x, lane = tid & 31, wid = tid >> 5;
    __shared__ float red[8][8];
    __shared__ float smax[8];

    float lm[8];
    #pragma unroll
    for (int h = 0; h < 8; ++h) lm[h] = -INFINITY;
    for (int r = s + tid; r < e; r += 256) {
        const float4* lp = reinterpret_cast<const float4*>(g_logits + (size_t)r * 8);
        float4 a = lp[0], b = lp[1];
        lm[0] = fmaxf(lm[0], a.x); lm[1] = fmaxf(lm[1], a.y);
        lm[2] = fmaxf(lm[2], a.z); lm[3] = fmaxf(lm[3], a.w);
        lm[4] = fmaxf(lm[4], b.x); lm[5] = fmaxf(lm[5], b.y);
        lm[6] = fmaxf(lm[6], b.z); lm[7] = fmaxf(lm[7], b.w);
    }
    #pragma unroll
    for (int h = 0; h < 8; ++h)
        #pragma unroll
        for (int o = 16; o > 0; o >>= 1)
            lm[h] = fmaxf(lm[h], __shfl_xor_sync(0xffffffffu, lm[h], o));
    if (lane == 0)
        #pragma unroll
        for (int h = 0; h < 8; ++h) red[wid][h] = lm[h];
    __syncthreads();
    if (tid < 8) {
        float m = red[0][tid];
        #pragma unroll
        for (int w = 1; w < 8; ++w) m = fmaxf(m, red[w][tid]);
        if (!(m >= -3.0e38f)) m = 0.f;
        smax[tid] = m;
        g_maxv[g * 8 + tid] = m;
    }
    __syncthreads();

    float mx[8], ls[8];
    #pragma unroll
    for (int h = 0; h < 8; ++h) { mx[h] = smax[h]; ls[h] = 0.f; }
    for (int r = s + tid; r < e; r += 256) {
        const float4* lp = reinterpret_cast<const float4*>(g_logits + (size_t)r * 8);
        float4 a = lp[0], b = lp[1];
        ls[0] += __expf(a.x - mx[0]); ls[1] += __expf(a.y - mx[1]);
        ls[2] += __expf(a.z - mx[2]); ls[3] += __expf(a.w - mx[3]);
        ls[4] += __expf(b.x - mx[4]); ls[5] += __expf(b.y - mx[5]);
        ls[6] += __expf(b.z - mx[6]); ls[7] += __expf(b.w - mx[7]);
    }
    #pragma unroll
    for (int h = 0; h < 8; ++h)
        #pragma unroll
        for (int o = 16; o > 0; o >>= 1)
            ls[h] += __shfl_xor_sync(0xffffffffu, ls[h], o);
    if (lane == 0)
        #pragma unroll
        for (int h = 0; h < 8; ++h) red[wid][h] = ls[h];
    __syncthreads();
    if (tid < 8) {
        float d = 0.f;
        #pragma unroll
        for (int w = 0; w < 8; ++w) d += red[w][tid];
        if (!(d > 0.f)) d = 1.f;
        g_denv[g * 8 + tid] = d;
    }
}

// ---------------------------------------------------------------------------
__global__ void k_weights(const int* __restrict__ batch,
                          float* __restrict__ w_out,
                          float* __restrict__ ent_out)
{
    int r = blockIdx.x * 256 + threadIdx.x;
    int b = batch[r];
    const float4* lp = reinterpret_cast<const float4*>(g_logits + (size_t)r * 8);
    const float4* mp = reinterpret_cast<const float4*>(g_maxv + b * 8);
    const float4* dp = reinterpret_cast<const float4*>(g_denv + b * 8);
    float4 l0 = lp[0], l1 = lp[1];
    float4 m0 = __ldg(mp), m1 = __ldg(mp + 1);
    float4 d0 = __ldg(dp), d1 = __ldg(dp + 1);

    float w[8];
    w[0] = __expf(l0.x - m0.x) / d0.x;
    w[1] = __expf(l0.y - m0.y) / d0.y;
    w[2] = __expf(l0.z - m0.z) / d0.z;
    w[3] = __expf(l0.w - m0.w) / d0.w;
    w[4] = __expf(l1.x - m1.x) / d1.x;
    w[5] = __expf(l1.y - m1.y) / d1.y;
    w[6] = __expf(l1.z - m1.z) / d1.z;
    w[7] = __expf(l1.w - m1.w) / d1.w;

    float4* op = reinterpret_cast<float4*>(w_out + (size_t)r * 8);
    op[0] = make_float4(w[0], w[1], w[2], w[3]);
    op[1] = make_float4(w[4], w[5], w[6], w[7]);

    float ent = 0.f;
    #pragma unroll
    for (int h = 0; h < 8; ++h) ent += w[h] * logf(w[h] + SM_EPS);
    #pragma unroll
    for (int o = 16; o > 0; o >>= 1)
        ent += __shfl_xor_sync(0xffffffffu, ent, o);
    if ((threadIdx.x & 31) == 0)
        atomicAdd(ent_out, -ent * (1.f / ((float)NG * (float)NHEADS)));
}

// ---------------------------------------------------------------------------
__global__ void k_scatter(const float* __restrict__ x,
                          const float* __restrict__ w,
                          float* __restrict__ gz)
{
    int g = blockIdx.x;
    int d = threadIdx.x;
    int s = g_off[g], e = g_off[g + 1];
    int h = d >> 6;
    float acc = 0.f;
    int r = s;
    for (; r + 4 <= e; r += 4) {
        float x0 = __ldg(x + (size_t)(r + 0) * HID + d);
        float x1 = __ldg(x + (size_t)(r + 1) * HID + d);
        float x2 = __ldg(x + (size_t)(r + 2) * HID + d);
        float x3 = __ldg(x + (size_t)(r + 3) * HID + d);
        float w0 = __ldg(w + (size_t)(r + 0) * 8 + h);
        float w1 = __ldg(w + (size_t)(r + 1) * 8 + h);
        float w2 = __ldg(w + (size_t)(r + 2) * 8 + h);
        float w3 = __ldg(w + (size_t)(r + 3) * 8 + h);
        acc += x0 * w0 + x1 * w1 + x2 * w2 + x3 * w3;
    }
    for (; r < e; ++r)
        acc += __ldg(x + (size_t)r * HID + d) * __ldg(w + (size_t)r * 8 + h);
    gz[(size_t)g * HID + d] = acc;
}

// ---------------------------------------------------------------------------
extern "C" void kernel_launch(void* const* d_in, const int* in_sizes, int n_in,
                              void* d_out, int out_size)
{
    (void)in_sizes; (void)n_in; (void)out_size;
    const float* x     = (const float*)d_in[0];
    const int*   batch = (const int*)  d_in[1];
    const float* gamma = (const float*)d_in[2];
    const float* beta  = (const float*)d_in[3];
    const float* W1    = (const float*)d_in[4];
    const float* b1    = (const float*)d_in[5];
    const float* W2    = (const float*)d_in[6];
    const float* b2    = (const float*)d_in[7];

    float* gz    = (float*)d_out;                    // [G, 512]
    float* w_out = gz + (size_t)NG * HID;            // [N, 8]
    float* ent   = w_out + (size_t)NROWS * NHEADS;   // [1]

    cudaFuncSetAttribute(k_logits_mma, cudaFuncAttributeMaxDynamicSharedMemorySize,
                         SMEM_TOT);

    k_init<<<1, 32>>>(ent);
    k_bounds<<<NROWS / 256, 256>>>(batch);
    k_prepw<<<HID, 256>>>(W1);
    k_logits_mma<<<NROWS / TM, NTHR, SMEM_TOT>>>(x, gamma, beta, b1, W2, b2);
    k_stats<<<NG, 256>>>();
    k_weights<<<NROWS / 256, 256>>>(batch, w_out, ent);
    k_scatter<<<NG, 512>>>(x, w_out, gz);
}

// round 12
// speedup vs baseline: 1.6086x; 1.1178x over previous
#include <cuda_runtime.h>
#include <cuda_fp16.h>
#include <math.h>
#include <stdint.h>

#define NROWS   262144
#define HID     512
#define NHEADS  8
#define NG      1024
#define NHID1   256
#define LN_EPS  1e-5f
#define SM_EPS  1e-8f

// ---- HMMA tiling: 2 CTAs/SM, each 64x256, 8 warps (grid 2x4, warp 32x64) ----
// Single fp16 product: x -> fp16, W1 -> fp16.
#define TM      64           // rows per CTA
#define TN      256          // full N
#define BK      32           // K per chunk
#define NCH     16           // 512 / 32
#define NTHR    256          // 8 warps

// A smem row stride: 32 fp16 + 8 pad = 40 fp16 = 80 B
#define ARS     80
// B smem row stride: 256 fp16 + 8 pad = 264 fp16 = 528 B
#define BRS     528

// per-buffer byte offsets
#define OFF_AH   0
#define OFF_BH   5120         // 64*80
#define BUF_SZ   22016        // 5120 + 32*528
// tail region
#define OFF_W2   44032        // 256*8 f32 = 8192
#define OFF_B1   52224        // 256 f32 = 1024
#define OFF_MU   53248        // 64 f32 = 256
#define OFF_RS   53504        // 64 f32 = 256
#define OFF_LG   53760        // 64*8 f32 = 2048
#define OFF_GS   55808        // 512 f32 = 2048
#define OFF_BT   57856        // 512 f32 = 2048
#define SMEM_TOT 59904

static __device__ float g_logits[(size_t)NROWS * NHEADS];
static __device__ float g_maxv[NG * NHEADS];
static __device__ float g_denv[NG * NHEADS];
static __device__ int   g_off[NG + 1];
// W1 fp16, row-major [512(k)][256(n)]
static __device__ __half g_Bh[HID * NHID1];

// ---------------------------------------------------------------------------
__device__ __forceinline__ uint32_t smem_u32(const void* p)
{
    uint32_t a;
    asm("{ .reg .u64 t; cvta.to.shared.u64 t, %1; cvt.u32.u64 %0, t; }"
        : "=r"(a) : "l"(p));
    return a;
}

__device__ __forceinline__ void ldsm4(uint32_t* r, uint32_t addr)
{
    asm volatile("ldmatrix.sync.aligned.m8n8.x4.shared.b16 {%0,%1,%2,%3}, [%4];"
                 : "=r"(r[0]), "=r"(r[1]), "=r"(r[2]), "=r"(r[3]) : "r"(addr));
}

__device__ __forceinline__ void ldsm4t(uint32_t* r, uint32_t addr)
{
    asm volatile("ldmatrix.sync.aligned.m8n8.x4.trans.shared.b16 {%0,%1,%2,%3}, [%4];"
                 : "=r"(r[0]), "=r"(r[1]), "=r"(r[2]), "=r"(r[3]) : "r"(addr));
}

__device__ __forceinline__ void mma16816(float* d, const uint32_t* a, const uint32_t* b)
{
    asm volatile(
        "mma.sync.aligned.m16n8k16.row.col.f32.f16.f16.f32 "
        "{%0,%1,%2,%3}, {%4,%5,%6,%7}, {%8,%9}, {%0,%1,%2,%3};"
        : "+f"(d[0]), "+f"(d[1]), "+f"(d[2]), "+f"(d[3])
        : "r"(a[0]), "r"(a[1]), "r"(a[2]), "r"(a[3]), "r"(b[0]), "r"(b[1]));
}

__device__ __forceinline__ void cp16(uint32_t dst, const void* src)
{
    asm volatile("cp.async.cg.shared.global [%0], [%1], 16;"
                 :: "r"(dst), "l"(src) : "memory");
}
#define CP_COMMIT() asm volatile("cp.async.commit_group;" ::: "memory")
#define CP_WAIT0()  asm volatile("cp.async.wait_group 0;" ::: "memory")

__device__ __forceinline__ unsigned pk(__half a, __half b)
{
    __half2 t = __halves2half2(a, b);
    return *reinterpret_cast<unsigned*>(&t);
}

// transform one float4 of x -> LN -> fp16, store 8B
__device__ __forceinline__ void xf_store(char* smc, uint32_t base, int row, int kq,
                                         float4 v, float mu, float rs,
                                         float4 gv, float4 bv)
{
    float n0 = (v.x - mu) * rs * gv.x + bv.x;
    float n1 = (v.y - mu) * rs * gv.y + bv.y;
    float n2 = (v.z - mu) * rs * gv.z + bv.z;
    float n3 = (v.w - mu) * rs * gv.w + bv.w;
    *reinterpret_cast<uint2*>(smc + base + OFF_AH + row * ARS + kq * 2) =
        make_uint2(pk(__float2half(n0), __float2half(n1)),
                   pk(__float2half(n2), __float2half(n3)));
}

// ---------------------------------------------------------------------------
__global__ void k_init(float* __restrict__ ent)
{
    if (threadIdx.x == 0) *ent = 0.f;
}

__global__ void k_bounds(const int* __restrict__ batch)
{
    int i = blockIdx.x * blockDim.x + threadIdx.x;
    if (i >= NROWS) return;
    int cur  = batch[i];
    int prev = (i == 0) ? -1 : batch[i - 1];
    for (int g = prev + 1; g <= cur; ++g) g_off[g] = i;
    if (i == NROWS - 1)
        for (int g = cur + 1; g <= NG; ++g) g_off[g] = NROWS;
}

__global__ void k_prepw(const float* __restrict__ W1)
{
    int i = blockIdx.x * 256 + threadIdx.x;
    g_Bh[i] = __float2half(W1[i]);
}

// ---------------------------------------------------------------------------
// Fused LayerNorm + GEMM1 (single fp16 HMMA) + SiLU + GEMM2
// 2 CTAs/SM x 8 warps, warp tile 32x64
// ---------------------------------------------------------------------------
__global__ __launch_bounds__(NTHR, 2)
void k_logits_mma(const float* __restrict__ x,
                  const float* __restrict__ gamma,
                  const float* __restrict__ beta,
                  const float* __restrict__ b1,
                  const float* __restrict__ W2,
                  const float* __restrict__ b2)
{
    extern __shared__ char smc[];
    float* smf = reinterpret_cast<float*>(smc);
    const uint32_t sb = smem_u32(smc);

    const int tid  = threadIdx.x;
    const int wid  = tid >> 5;
    const int lane = tid & 31;
    const int m_base = blockIdx.x * TM;

    // tail-region fills
    for (int i = tid; i < 2048; i += NTHR) smf[OFF_W2 / 4 + i] = W2[i];
    if (tid < 256) smf[OFF_B1 / 4 + tid] = b1[tid];
    for (int i = tid; i < HID; i += NTHR) {
        smf[OFF_GS / 4 + i] = gamma[i];
        smf[OFF_BT / 4 + i] = beta[i];
    }
    for (int i = tid; i < TM * NHEADS; i += NTHR)
        smf[OFF_LG / 4 + i] = b2[i & 7];

    // ---- LayerNorm stats: 4 threads per row ----
    {
        int row = tid >> 2, part = tid & 3;
        const float4* xr = reinterpret_cast<const float4*>(
            x + (size_t)(m_base + row) * HID) + part * 32;
        float s = 0.f, s2 = 0.f;
        #pragma unroll 8
        for (int i = 0; i < 32; ++i) {
            float4 v = __ldg(xr + i);
            s  += v.x + v.y + v.z + v.w;
            s2 += v.x * v.x + v.y * v.y + v.z * v.z + v.w * v.w;
        }
        s  += __shfl_xor_sync(0xffffffffu, s, 1);
        s  += __shfl_xor_sync(0xffffffffu, s, 2);
        s2 += __shfl_xor_sync(0xffffffffu, s2, 1);
        s2 += __shfl_xor_sync(0xffffffffu, s2, 2);
        if (!part) {
            float m = s * (1.f / HID);
            float v = s2 * (1.f / HID) - m * m;
            smf[OFF_MU / 4 + row] = m;
            smf[OFF_RS / 4 + row] = rsqrtf(v + LN_EPS);
        }
    }
    __syncthreads();

    // per-thread A geometry: 2 slots, rows tid>>3 + {0,32}, same kq
    const int a_kq = (tid & 7) * 4;
    int   a_row[2];
    float a_mu[2], a_rs[2];
    const float* xp[2];
    #pragma unroll
    for (int s = 0; s < 2; ++s) {
        a_row[s] = (tid >> 3) + s * 32;
        a_mu[s]  = smf[OFF_MU / 4 + a_row[s]];
        a_rs[s]  = smf[OFF_RS / 4 + a_row[s]];
        xp[s]    = x + (size_t)(m_base + a_row[s]) * HID + a_kq;
    }

    // B copy geometry: 4 float4 slots (32 rows x 512 B = 1024 float4)
    int b_r[4], b_c[4];
    #pragma unroll
    for (int s = 0; s < 4; ++s) {
        int j = tid + s * 256;
        b_r[s] = j >> 5;
        b_c[s] = (j & 31) * 16;
    }

    // warp MMA geometry: grid 2(m) x 4(n), warp tile 32x64
    const int wm = (wid >> 2) * 32;
    const int wn = (wid & 3) * 64;
    const uint32_t a_lds = (uint32_t)((wm + (lane & 15)) * ARS + (lane >> 4) * 16);
    const uint32_t b_lds = (uint32_t)((lane & 15) * BRS + (wn + (lane >> 4) * 8) * 2);

    float acc[2][8][4];
    #pragma unroll
    for (int mt = 0; mt < 2; ++mt)
        #pragma unroll
        for (int nt = 0; nt < 8; ++nt)
            #pragma unroll
            for (int e = 0; e < 4; ++e) acc[mt][nt][e] = 0.f;

    float4 xr[2];

    // ---- prologue: fill buffer 0 (chunk 0) ----
    {
        #pragma unroll
        for (int s = 0; s < 4; ++s)
            cp16(sb + OFF_BH + b_r[s] * BRS + b_c[s],
                 (const char*)g_Bh + b_r[s] * 512 + b_c[s]);
        CP_COMMIT();
        #pragma unroll
        for (int s = 0; s < 2; ++s)
            xr[s] = __ldg(reinterpret_cast<const float4*>(xp[s]));
        const float4 gv = *reinterpret_cast<const float4*>(&smf[OFF_GS / 4 + a_kq]);
        const float4 bv = *reinterpret_cast<const float4*>(&smf[OFF_BT / 4 + a_kq]);
        #pragma unroll
        for (int s = 0; s < 2; ++s)
            xf_store(smc, 0, a_row[s], a_kq, xr[s], a_mu[s], a_rs[s], gv, bv);
        CP_WAIT0();
    }
    __syncthreads();

    // ---- mainloop ----
    for (int t = 0; t < NCH; ++t) {
        const uint32_t bufc = (uint32_t)((t & 1) * BUF_SZ);
        const uint32_t bufn = (uint32_t)(((t + 1) & 1) * BUF_SZ);
        const bool more = (t < NCH - 1);

        if (more) {
            const char* gh = (const char*)g_Bh + (size_t)(t + 1) * 32 * 512;
            #pragma unroll
            for (int s = 0; s < 4; ++s)
                cp16(sb + bufn + OFF_BH + b_r[s] * BRS + b_c[s], gh + b_r[s] * 512 + b_c[s]);
            CP_COMMIT();
            #pragma unroll
            for (int s = 0; s < 2; ++s)
                xr[s] = __ldg(reinterpret_cast<const float4*>(xp[s] + (t + 1) * BK));
        }

        // MMA ks = 0
        {
            uint32_t ah[2][4];
            #pragma unroll
            for (int mt = 0; mt < 2; ++mt)
                ldsm4(ah[mt], sb + bufc + a_lds + (uint32_t)(mt * 16 * ARS) + OFF_AH);
            #pragma unroll
            for (int np = 0; np < 4; ++np) {
                uint32_t bh[4];
                uint32_t bo = sb + bufc + b_lds + (uint32_t)(np * 32);
                ldsm4t(bh, bo + OFF_BH);
                #pragma unroll
                for (int mt = 0; mt < 2; ++mt) {
                    mma16816(acc[mt][2 * np],     ah[mt], bh);
                    mma16816(acc[mt][2 * np + 1], ah[mt], bh + 2);
                }
            }
        }

        // transform + store A(t+1) (overlaps tensor-pipe drain of ks=0)
        if (more) {
            const int kb = (t + 1) * BK;
            const float4 gv = *reinterpret_cast<const float4*>(&smf[OFF_GS / 4 + kb + a_kq]);
            const float4 bv = *reinterpret_cast<const float4*>(&smf[OFF_BT / 4 + kb + a_kq]);
            #pragma unroll
            for (int s = 0; s < 2; ++s)
                xf_store(smc, bufn, a_row[s], a_kq, xr[s], a_mu[s], a_rs[s], gv, bv);
        }

        // MMA ks = 1
        {
            uint32_t ah[2][4];
            #pragma unroll
            for (int mt = 0; mt < 2; ++mt)
                ldsm4(ah[mt], sb + bufc + a_lds + (uint32_t)(mt * 16 * ARS + 32) + OFF_AH);
            #pragma unroll
            for (int np = 0; np < 4; ++np) {
                uint32_t bh[4];
                uint32_t bo = sb + bufc + b_lds + (uint32_t)(16 * BRS + np * 32);
                ldsm4t(bh, bo + OFF_BH);
                #pragma unroll
                for (int mt = 0; mt < 2; ++mt) {
                    mma16816(acc[mt][2 * np],     ah[mt], bh);
                    mma16816(acc[mt][2 * np + 1], ah[mt], bh + 2);
                }
            }
        }

        if (more) CP_WAIT0();
        __syncthreads();
    }

    // ---- epilogue: SiLU + GEMM2 (h @ W2), accumulate logits in smem ----
    const int g = lane >> 2, q = lane & 3;
    float pacc[4][8];
    #pragma unroll
    for (int r = 0; r < 4; ++r)
        #pragma unroll
        for (int h = 0; h < 8; ++h) pacc[r][h] = 0.f;

    #pragma unroll
    for (int nt = 0; nt < 8; ++nt) {
        const int c0 = wn + nt * 8 + q * 2;
        const float4 w0a = *reinterpret_cast<const float4*>(&smf[OFF_W2 / 4 + c0 * 8]);
        const float4 w0b = *reinterpret_cast<const float4*>(&smf[OFF_W2 / 4 + c0 * 8 + 4]);
        const float4 w1a = *reinterpret_cast<const float4*>(&smf[OFF_W2 / 4 + (c0 + 1) * 8]);
        const float4 w1b = *reinterpret_cast<const float4*>(&smf[OFF_W2 / 4 + (c0 + 1) * 8 + 4]);
        const float b1c0 = smf[OFF_B1 / 4 + c0];
        const float b1c1 = smf[OFF_B1 / 4 + c0 + 1];
        #pragma unroll
        for (int mt = 0; mt < 2; ++mt) {
            #pragma unroll
            for (int e = 0; e < 4; ++e) {
                float hv = acc[mt][nt][e] + ((e & 1) ? b1c1 : b1c0);
                float sv = hv / (1.f + __expf(-hv));
                const int r = mt * 2 + (e >> 1);
                const float4 wa = (e & 1) ? w1a : w0a;
                const float4 wb = (e & 1) ? w1b : w0b;
                pacc[r][0] += sv * wa.x; pacc[r][1] += sv * wa.y;
                pacc[r][2] += sv * wa.z; pacc[r][3] += sv * wa.w;
                pacc[r][4] += sv * wb.x; pacc[r][5] += sv * wb.y;
                pacc[r][6] += sv * wb.z; pacc[r][7] += sv * wb.w;
            }
        }
    }
    #pragma unroll
    for (int r = 0; r < 4; ++r)
        #pragma unroll
        for (int h = 0; h < 8; ++h) {
            pacc[r][h] += __shfl_xor_sync(0xffffffffu, pacc[r][h], 1);
            pacc[r][h] += __shfl_xor_sync(0xffffffffu, pacc[r][h], 2);
        }
    if (q == 0) {
        #pragma unroll
        for (int r = 0; r < 4; ++r) {
            const int row = wm + (r >> 1) * 16 + (r & 1) * 8 + g;
            #pragma unroll
            for (int h = 0; h < 8; ++h)
                atomicAdd(&smf[OFF_LG / 4 + row * 8 + h], pacc[r][h]);
        }
    }
    __syncthreads();

    if (tid < TM) {
        const float4* src = reinterpret_cast<const float4*>(&smf[OFF_LG / 4 + tid * 8]);
        float4* dst = reinterpret_cast<float4*>(g_logits + (size_t)(m_base + tid) * 8);
        dst[0] = src[0];
        dst[1] = src[1];
    }
}

// ---------------------------------------------------------------------------
__global__ void k_stats()
{
    int g = blockIdx.x;
    int s = g_off[g], e = g_off[g + 1];
    int tid = threadIdx.x, lane = tid & 31, wid = tid >> 5;
    __shared__ float red[8][8];
    __shared__ float smax[8];

    float lm[8];
    #pragma unroll
    for (int h = 0; h < 8; ++h) lm[h] = -INFINITY;
    for (int r = s + tid; r < e; r += 256) {
        const float4* lp = reinterpret_cast<const float4*>(g_logits + (size_t)r * 8);
        float4 a = lp[0], b = lp[1];
        lm[0] = fmaxf(lm[0], a.x); lm[1] = fmaxf(lm[1], a.y);
        lm[2] = fmaxf(lm[2], a.z); lm[3] = fmaxf(lm[3], a.w);
        lm[4] = fmaxf(lm[4], b.x); lm[5] = fmaxf(lm[5], b.y);
        lm[6] = fmaxf(lm[6], b.z); lm[7] = fmaxf(lm[7], b.w);
    }
    #pragma unroll
    for (int h = 0; h < 8; ++h)
        #pragma unroll
        for (int o = 16; o > 0; o >>= 1)
            lm[h] = fmaxf(lm[h], __shfl_xor_sync(0xffffffffu, lm[h], o));
    if (lane == 0)
        #pragma unroll
        for (int h = 0; h < 8; ++h) red[wid][h] = lm[h];
    __syncthreads();
    if (tid < 8) {
        float m = red[0][tid];
        #pragma unroll
        for (int w = 1; w < 8; ++w) m = fmaxf(m, red[w][tid]);
        if (!(m >= -3.0e38f)) m = 0.f;
        smax[tid] = m;
        g_maxv[g * 8 + tid] = m;
    }
    __syncthreads();

    float mx[8], ls[8];
    #pragma unroll
    for (int h = 0; h < 8; ++h) { mx[h] = smax[h]; ls[h] = 0.f; }
    for (int r = s + tid; r < e; r += 256) {
        const float4* lp = reinterpret_cast<const float4*>(g_logits + (size_t)r * 8);
        float4 a = lp[0], b = lp[1];
        ls[0] += __expf(a.x - mx[0]); ls[1] += __expf(a.y - mx[1]);
        ls[2] += __expf(a.z - mx[2]); ls[3] += __expf(a.w - mx[3]);
        ls[4] += __expf(b.x - mx[4]); ls[5] += __expf(b.y - mx[5]);
        ls[6] += __expf(b.z - mx[6]); ls[7] += __expf(b.w - mx[7]);
    }
    #pragma unroll
    for (int h = 0; h < 8; ++h)
        #pragma unroll
        for (int o = 16; o > 0; o >>= 1)
            ls[h] += __shfl_xor_sync(0xffffffffu, ls[h], o);
    if (lane == 0)
        #pragma unroll
        for (int h = 0; h < 8; ++h) red[wid][h] = ls[h];
    __syncthreads();
    if (tid < 8) {
        float d = 0.f;
        #pragma unroll
        for (int w = 0; w < 8; ++w) d += red[w][tid];
        if (!(d > 0.f)) d = 1.f;
        g_denv[g * 8 + tid] = d;
    }
}

// ---------------------------------------------------------------------------
__global__ void k_weights(const int* __restrict__ batch,
                          float* __restrict__ w_out,
                          float* __restrict__ ent_out)
{
    int r = blockIdx.x * 256 + threadIdx.x;
    int b = batch[r];
    const float4* lp = reinterpret_cast<const float4*>(g_logits + (size_t)r * 8);
    const float4* mp = reinterpret_cast<const float4*>(g_maxv + b * 8);
    const float4* dp = reinterpret_cast<const float4*>(g_denv + b * 8);
    float4 l0 = lp[0], l1 = lp[1];
    float4 m0 = __ldg(mp), m1 = __ldg(mp + 1);
    float4 d0 = __ldg(dp), d1 = __ldg(dp + 1);

    float w[8];
    w[0] = __expf(l0.x - m0.x) / d0.x;
    w[1] = __expf(l0.y - m0.y) / d0.y;
    w[2] = __expf(l0.z - m0.z) / d0.z;
    w[3] = __expf(l0.w - m0.w) / d0.w;
    w[4] = __expf(l1.x - m1.x) / d1.x;
    w[5] = __expf(l1.y - m1.y) / d1.y;
    w[6] = __expf(l1.z - m1.z) / d1.z;
    w[7] = __expf(l1.w - m1.w) / d1.w;

    float4* op = reinterpret_cast<float4*>(w_out + (size_t)r * 8);
    op[0] = make_float4(w[0], w[1], w[2], w[3]);
    op[1] = make_float4(w[4], w[5], w[6], w[7]);

    float ent = 0.f;
    #pragma unroll
    for (int h = 0; h < 8; ++h) ent += w[h] * logf(w[h] + SM_EPS);
    #pragma unroll
    for (int o = 16; o > 0; o >>= 1)
        ent += __shfl_xor_sync(0xffffffffu, ent, o);
    if ((threadIdx.x & 31) == 0)
        atomicAdd(ent_out, -ent * (1.f / ((float)NG * (float)NHEADS)));
}

// ---------------------------------------------------------------------------
__global__ void k_scatter(const float* __restrict__ x,
                          const float* __restrict__ w,
                          float* __restrict__ gz)
{
    int g = blockIdx.x;
    int d = threadIdx.x;
    int s = g_off[g], e = g_off[g + 1];
    int h = d >> 6;
    float acc = 0.f;
    int r = s;
    for (; r + 4 <= e; r += 4) {
        float x0 = __ldg(x + (size_t)(r + 0) * HID + d);
        float x1 = __ldg(x + (size_t)(r + 1) * HID + d);
        float x2 = __ldg(x + (size_t)(r + 2) * HID + d);
        float x3 = __ldg(x + (size_t)(r + 3) * HID + d);
        float w0 = __ldg(w + (size_t)(r + 0) * 8 + h);
        float w1 = __ldg(w + (size_t)(r + 1) * 8 + h);
        float w2 = __ldg(w + (size_t)(r + 2) * 8 + h);
        float w3 = __ldg(w + (size_t)(r + 3) * 8 + h);
        acc += x0 * w0 + x1 * w1 + x2 * w2 + x3 * w3;
    }
    for (; r < e; ++r)
        acc += __ldg(x + (size_t)r * HID + d) * __ldg(w + (size_t)r * 8 + h);
    gz[(size_t)g * HID + d] = acc;
}

// ---------------------------------------------------------------------------
extern "C" void kernel_launch(void* const* d_in, const int* in_sizes, int n_in,
                              void* d_out, int out_size)
{
    (void)in_sizes; (void)n_in; (void)out_size;
    const float* x     = (const float*)d_in[0];
    const int*   batch = (const int*)  d_in[1];
    const float* gamma = (const float*)d_in[2];
    const float* beta  = (const float*)d_in[3];
    const float* W1    = (const float*)d_in[4];
    const float* b1    = (const float*)d_in[5];
    const float* W2    = (const float*)d_in[6];
    const float* b2    = (const float*)d_in[7];

    float* gz    = (float*)d_out;                    // [G, 512]
    float* w_out = gz + (size_t)NG * HID;            // [N, 8]
    float* ent   = w_out + (size_t)NROWS * NHEADS;   // [1]

    cudaFuncSetAttribute(k_logits_mma, cudaFuncAttributeMaxDynamicSharedMemorySize,
                         SMEM_TOT);

    k_init<<<1, 32>>>(ent);
    k_bounds<<<NROWS / 256, 256>>>(batch);
    k_prepw<<<HID, 256>>>(W1);
    k_logits_mma<<<NROWS / TM, NTHR, SMEM_TOT>>>(x, gamma, beta, b1, W2, b2);
    k_stats<<<NG, 256>>>();
    k_weights<<<NROWS / 256, 256>>>(batch, w_out, ent);
    k_scatter<<<NG, 512>>>(x, w_out, gz);
}

// round 13
// speedup vs baseline: 1.6124x; 1.0024x over previous
#include <cuda_runtime.h>
#include <cuda_fp16.h>
#include <math.h>
#include <stdint.h>

#define NROWS   262144
#define HID     512
#define NHEADS  8
#define NG      1024
#define NHID1   256
#define LN_EPS  1e-5f
#define SM_EPS  1e-8f

// ---- HMMA tiling: 2 CTAs/SM, each 64x256, 8 warps (grid 2x4, warp 32x64) ----
// Single fp16 product: x -> fp16, W1 -> fp16.
#define TM      64           // rows per CTA
#define TN      256          // full N
#define BK      32           // K per chunk
#define NCH     16           // 512 / 32
#define NTHR    256          // 8 warps

// A smem row stride: 32 fp16 + 8 pad = 40 fp16 = 80 B
#define ARS     80
// B smem row stride: 256 fp16 + 8 pad = 264 fp16 = 528 B
#define BRS     528

// per-buffer byte offsets
#define OFF_AH   0
#define OFF_BH   5120         // 64*80
#define BUF_SZ   22016        // 5120 + 32*528
// tail region
#define OFF_W2   44032        // 256*8 f32 = 8192
#define OFF_B1   52224        // 256 f32 = 1024
#define OFF_MU   53248        // 64 f32 = 256
#define OFF_RS   53504        // 64 f32 = 256
#define OFF_LG   53760        // 64*8 f32 = 2048
#define OFF_GS   55808        // 512 f32 = 2048
#define OFF_BT   57856        // 512 f32 = 2048
#define SMEM_TOT 59904

static __device__ float g_logits[(size_t)NROWS * NHEADS];
static __device__ float g_maxv[NG * NHEADS];
static __device__ float g_denv[NG * NHEADS];
static __device__ int   g_off[NG + 1];
// W1 fp16, row-major [512(k)][256(n)]
static __device__ __half g_Bh[HID * NHID1];

// ---------------------------------------------------------------------------
__device__ __forceinline__ uint32_t smem_u32(const void* p)
{
    uint32_t a;
    asm("{ .reg .u64 t; cvta.to.shared.u64 t, %1; cvt.u32.u64 %0, t; }"
        : "=r"(a) : "l"(p));
    return a;
}

__device__ __forceinline__ void ldsm4(uint32_t* r, uint32_t addr)
{
    asm volatile("ldmatrix.sync.aligned.m8n8.x4.shared.b16 {%0,%1,%2,%3}, [%4];"
                 : "=r"(r[0]), "=r"(r[1]), "=r"(r[2]), "=r"(r[3]) : "r"(addr));
}

__device__ __forceinline__ void ldsm4t(uint32_t* r, uint32_t addr)
{
    asm volatile("ldmatrix.sync.aligned.m8n8.x4.trans.shared.b16 {%0,%1,%2,%3}, [%4];"
                 : "=r"(r[0]), "=r"(r[1]), "=r"(r[2]), "=r"(r[3]) : "r"(addr));
}

__device__ __forceinline__ void mma16816(float* d, const uint32_t* a, const uint32_t* b)
{
    asm volatile(
        "mma.sync.aligned.m16n8k16.row.col.f32.f16.f16.f32 "
        "{%0,%1,%2,%3}, {%4,%5,%6,%7}, {%8,%9}, {%0,%1,%2,%3};"
        : "+f"(d[0]), "+f"(d[1]), "+f"(d[2]), "+f"(d[3])
        : "r"(a[0]), "r"(a[1]), "r"(a[2]), "r"(a[3]), "r"(b[0]), "r"(b[1]));
}

__device__ __forceinline__ void cp16(uint32_t dst, const void* src)
{
    asm volatile("cp.async.cg.shared.global [%0], [%1], 16;"
                 :: "r"(dst), "l"(src) : "memory");
}
#define CP_COMMIT() asm volatile("cp.async.commit_group;" ::: "memory")
#define CP_WAIT0()  asm volatile("cp.async.wait_group 0;" ::: "memory")

__device__ __forceinline__ unsigned pk(__half a, __half b)
{
    __half2 t = __halves2half2(a, b);
    return *reinterpret_cast<unsigned*>(&t);
}

// transform one float4 of x -> LN -> fp16, store 8B
__device__ __forceinline__ void xf_store(char* smc, uint32_t base, int row, int kq,
                                         float4 v, float mu, float rs,
                                         float4 gv, float4 bv)
{
    float n0 = (v.x - mu) * rs * gv.x + bv.x;
    float n1 = (v.y - mu) * rs * gv.y + bv.y;
    float n2 = (v.z - mu) * rs * gv.z + bv.z;
    float n3 = (v.w - mu) * rs * gv.w + bv.w;
    *reinterpret_cast<uint2*>(smc + base + OFF_AH + row * ARS + kq * 2) =
        make_uint2(pk(__float2half(n0), __float2half(n1)),
                   pk(__float2half(n2), __float2half(n3)));
}

// ---------------------------------------------------------------------------
__global__ void k_init(float* __restrict__ ent)
{
    if (threadIdx.x == 0) *ent = 0.f;
}

__global__ void k_bounds(const int* __restrict__ batch)
{
    int i = blockIdx.x * blockDim.x + threadIdx.x;
    if (i >= NROWS) return;
    int cur  = batch[i];
    int prev = (i == 0) ? -1 : batch[i - 1];
    for (int g = prev + 1; g <= cur; ++g) g_off[g] = i;
    if (i == NROWS - 1)
        for (int g = cur + 1; g <= NG; ++g) g_off[g] = NROWS;
}

__global__ void k_prepw(const float* __restrict__ W1)
{
    int i = blockIdx.x * 256 + threadIdx.x;
    g_Bh[i] = __float2half(W1[i]);
}

// ---------------------------------------------------------------------------
// Fused LayerNorm + GEMM1 (single fp16 HMMA) + SiLU + GEMM2
// 2 CTAs/SM x 8 warps, warp tile 32x64
// ---------------------------------------------------------------------------
__global__ __launch_bounds__(NTHR, 2)
void k_logits_mma(const float* __restrict__ x,
                  const float* __restrict__ gamma,
                  const float* __restrict__ beta,
                  const float* __restrict__ b1,
                  const float* __restrict__ W2,
                  const float* __restrict__ b2)
{
    extern __shared__ char smc[];
    float* smf = reinterpret_cast<float*>(smc);
    const uint32_t sb = smem_u32(smc);

    const int tid  = threadIdx.x;
    const int wid  = tid >> 5;
    const int lane = tid & 31;
    const int m_base = blockIdx.x * TM;

    // tail-region fills
    for (int i = tid; i < 2048; i += NTHR) smf[OFF_W2 / 4 + i] = W2[i];
    if (tid < 256) smf[OFF_B1 / 4 + tid] = b1[tid];
    for (int i = tid; i < HID; i += NTHR) {
        smf[OFF_GS / 4 + i] = gamma[i];
        smf[OFF_BT / 4 + i] = beta[i];
    }
    for (int i = tid; i < TM * NHEADS; i += NTHR)
        smf[OFF_LG / 4 + i] = b2[i & 7];

    // ---- LayerNorm stats: 4 threads per row ----
    {
        int row = tid >> 2, part = tid & 3;
        const float4* xr = reinterpret_cast<const float4*>(
            x + (size_t)(m_base + row) * HID) + part * 32;
        float s = 0.f, s2 = 0.f;
        #pragma unroll 8
        for (int i = 0; i < 32; ++i) {
            float4 v = __ldg(xr + i);
            s  += v.x + v.y + v.z + v.w;
            s2 += v.x * v.x + v.y * v.y + v.z * v.z + v.w * v.w;
        }
        s  += __shfl_xor_sync(0xffffffffu, s, 1);
        s  += __shfl_xor_sync(0xffffffffu, s, 2);
        s2 += __shfl_xor_sync(0xffffffffu, s2, 1);
        s2 += __shfl_xor_sync(0xffffffffu, s2, 2);
        if (!part) {
            float m = s * (1.f / HID);
            float v = s2 * (1.f / HID) - m * m;
            smf[OFF_MU / 4 + row] = m;
            smf[OFF_RS / 4 + row] = rsqrtf(v + LN_EPS);
        }
    }
    __syncthreads();

    // per-thread A geometry: 2 slots, rows tid>>3 + {0,32}, same kq
    const int a_kq = (tid & 7) * 4;
    int   a_row[2];
    float a_mu[2], a_rs[2];
    const float* xp[2];
    #pragma unroll
    for (int s = 0; s < 2; ++s) {
        a_row[s] = (tid >> 3) + s * 32;
        a_mu[s]  = smf[OFF_MU / 4 + a_row[s]];
        a_rs[s]  = smf[OFF_RS / 4 + a_row[s]];
        xp[s]    = x + (size_t)(m_base + a_row[s]) * HID + a_kq;
    }

    // B copy geometry: 4 float4 slots (32 rows x 512 B = 1024 float4)
    int b_r[4], b_c[4];
    #pragma unroll
    for (int s = 0; s < 4; ++s) {
        int j = tid + s * 256;
        b_r[s] = j >> 5;
        b_c[s] = (j & 31) * 16;
    }

    // warp MMA geometry: grid 2(m) x 4(n), warp tile 32x64
    const int wm = (wid >> 2) * 32;
    const int wn = (wid & 3) * 64;
    const uint32_t a_lds = (uint32_t)((wm + (lane & 15)) * ARS + (lane >> 4) * 16);
    const uint32_t b_lds = (uint32_t)((lane & 15) * BRS + (wn + (lane >> 4) * 8) * 2);

    float acc[2][8][4];
    #pragma unroll
    for (int mt = 0; mt < 2; ++mt)
        #pragma unroll
        for (int nt = 0; nt < 8; ++nt)
            #pragma unroll
            for (int e = 0; e < 4; ++e) acc[mt][nt][e] = 0.f;

    float4 xr[2];

    // ---- prologue: fill buffer 0 (chunk 0) ----
    {
        #pragma unroll
        for (int s = 0; s < 4; ++s)
            cp16(sb + OFF_BH + b_r[s] * BRS + b_c[s],
                 (const char*)g_Bh + b_r[s] * 512 + b_c[s]);
        CP_COMMIT();
        #pragma unroll
        for (int s = 0; s < 2; ++s)
            xr[s] = __ldg(reinterpret_cast<const float4*>(xp[s]));
        const float4 gv = *reinterpret_cast<const float4*>(&smf[OFF_GS / 4 + a_kq]);
        const float4 bv = *reinterpret_cast<const float4*>(&smf[OFF_BT / 4 + a_kq]);
        #pragma unroll
        for (int s = 0; s < 2; ++s)
            xf_store(smc, 0, a_row[s], a_kq, xr[s], a_mu[s], a_rs[s], gv, bv);
        CP_WAIT0();
    }
    __syncthreads();

    // ---- mainloop ----
    for (int t = 0; t < NCH; ++t) {
        const uint32_t bufc = (uint32_t)((t & 1) * BUF_SZ);
        const uint32_t bufn = (uint32_t)(((t + 1) & 1) * BUF_SZ);
        const bool more = (t < NCH - 1);

        if (more) {
            const char* gh = (const char*)g_Bh + (size_t)(t + 1) * 32 * 512;
            #pragma unroll
            for (int s = 0; s < 4; ++s)
                cp16(sb + bufn + OFF_BH + b_r[s] * BRS + b_c[s], gh + b_r[s] * 512 + b_c[s]);
            CP_COMMIT();
            #pragma unroll
            for (int s = 0; s < 2; ++s)
                xr[s] = __ldg(reinterpret_cast<const float4*>(xp[s] + (t + 1) * BK));
        }

        // MMA ks = 0
        {
            uint32_t ah[2][4];
            #pragma unroll
            for (int mt = 0; mt < 2; ++mt)
                ldsm4(ah[mt], sb + bufc + a_lds + (uint32_t)(mt * 16 * ARS) + OFF_AH);
            #pragma unroll
            for (int np = 0; np < 4; ++np) {
                uint32_t bh[4];
                uint32_t bo = sb + bufc + b_lds + (uint32_t)(np * 32);
                ldsm4t(bh, bo + OFF_BH);
                #pragma unroll
                for (int mt = 0; mt < 2; ++mt) {
                    mma16816(acc[mt][2 * np],     ah[mt], bh);
                    mma16816(acc[mt][2 * np + 1], ah[mt], bh + 2);
                }
            }
        }

        // transform + store A(t+1) (overlaps tensor-pipe drain of ks=0)
        if (more) {
            const int kb = (t + 1) * BK;
            const float4 gv = *reinterpret_cast<const float4*>(&smf[OFF_GS / 4 + kb + a_kq]);
            const float4 bv = *reinterpret_cast<const float4*>(&smf[OFF_BT / 4 + kb + a_kq]);
            #pragma unroll
            for (int s = 0; s < 2; ++s)
                xf_store(smc, bufn, a_row[s], a_kq, xr[s], a_mu[s], a_rs[s], gv, bv);
        }

        // MMA ks = 1
        {
            uint32_t ah[2][4];
            #pragma unroll
            for (int mt = 0; mt < 2; ++mt)
                ldsm4(ah[mt], sb + bufc + a_lds + (uint32_t)(mt * 16 * ARS + 32) + OFF_AH);
            #pragma unroll
            for (int np = 0; np < 4; ++np) {
                uint32_t bh[4];
                uint32_t bo = sb + bufc + b_lds + (uint32_t)(16 * BRS + np * 32);
                ldsm4t(bh, bo + OFF_BH);
                #pragma unroll
                for (int mt = 0; mt < 2; ++mt) {
                    mma16816(acc[mt][2 * np],     ah[mt], bh);
                    mma16816(acc[mt][2 * np + 1], ah[mt], bh + 2);
                }
            }
        }

        if (more) CP_WAIT0();
        __syncthreads();
    }

    // ---- epilogue: SiLU + GEMM2 (h @ W2), accumulate logits in smem ----
    const int g = lane >> 2, q = lane & 3;
    float pacc[4][8];
    #pragma unroll
    for (int r = 0; r < 4; ++r)
        #pragma unroll
        for (int h = 0; h < 8; ++h) pacc[r][h] = 0.f;

    #pragma unroll
    for (int nt = 0; nt < 8; ++nt) {
        const int c0 = wn + nt * 8 + q * 2;
        const float4 w0a = *reinterpret_cast<const float4*>(&smf[OFF_W2 / 4 + c0 * 8]);
        const float4 w0b = *reinterpret_cast<const float4*>(&smf[OFF_W2 / 4 + c0 * 8 + 4]);
        const float4 w1a = *reinterpret_cast<const float4*>(&smf[OFF_W2 / 4 + (c0 + 1) * 8]);
        const float4 w1b = *reinterpret_cast<const float4*>(&smf[OFF_W2 / 4 + (c0 + 1) * 8 + 4]);
        const float b1c0 = smf[OFF_B1 / 4 + c0];
        const float b1c1 = smf[OFF_B1 / 4 + c0 + 1];
        #pragma unroll
        for (int mt = 0; mt < 2; ++mt) {
            #pragma unroll
            for (int e = 0; e < 4; ++e) {
                float hv = acc[mt][nt][e] + ((e & 1) ? b1c1 : b1c0);
                float sv = hv / (1.f + __expf(-hv));
                const int r = mt * 2 + (e >> 1);
                const float4 wa = (e & 1) ? w1a : w0a;
                const float4 wb = (e & 1) ? w1b : w0b;
                pacc[r][0] += sv * wa.x; pacc[r][1] += sv * wa.y;
                pacc[r][2] += sv * wa.z; pacc[r][3] += sv * wa.w;
                pacc[r][4] += sv * wb.x; pacc[r][5] += sv * wb.y;
                pacc[r][6] += sv * wb.z; pacc[r][7] += sv * wb.w;
            }
        }
    }
    #pragma unroll
    for (int r = 0; r < 4; ++r)
        #pragma unroll
        for (int h = 0; h < 8; ++h) {
            pacc[r][h] += __shfl_xor_sync(0xffffffffu, pacc[r][h], 1);
            pacc[r][h] += __shfl_xor_sync(0xffffffffu, pacc[r][h], 2);
        }
    if (q == 0) {
        #pragma unroll
        for (int r = 0; r < 4; ++r) {
            const int row = wm + (r >> 1) * 16 + (r & 1) * 8 + g;
            #pragma unroll
            for (int h = 0; h < 8; ++h)
                atomicAdd(&smf[OFF_LG / 4 + row * 8 + h], pacc[r][h]);
        }
    }
    __syncthreads();

    if (tid < TM) {
        const float4* src = reinterpret_cast<const float4*>(&smf[OFF_LG / 4 + tid * 8]);
        float4* dst = reinterpret_cast<float4*>(g_logits + (size_t)(m_base + tid) * 8);
        dst[0] = src[0];
        dst[1] = src[1];
    }
}

// ---------------------------------------------------------------------------
__global__ void k_stats()
{
    int g = blockIdx.x;
    int s = g_off[g], e = g_off[g + 1];
    int tid = threadIdx.x, lane = tid & 31, wid = tid >> 5;
    __shared__ float red[8][8];
    __shared__ float smax[8];

    float lm[8];
    #pragma unroll
    for (int h = 0; h < 8; ++h) lm[h] = -INFINITY;
    for (int r = s + tid; r < e; r += 256) {
        const float4* lp = reinterpret_cast<const float4*>(g_logits + (size_t)r * 8);
        float4 a = lp[0], b = lp[1];
        lm[0] = fmaxf(lm[0], a.x); lm[1] = fmaxf(lm[1], a.y);
        lm[2] = fmaxf(lm[2], a.z); lm[3] = fmaxf(lm[3], a.w);
        lm[4] = fmaxf(lm[4], b.x); lm[5] = fmaxf(lm[5], b.y);
        lm[6] = fmaxf(lm[6], b.z); lm[7] = fmaxf(lm[7], b.w);
    }
    #pragma unroll
    for (int h = 0; h < 8; ++h)
        #pragma unroll
        for (int o = 16; o > 0; o >>= 1)
            lm[h] = fmaxf(lm[h], __shfl_xor_sync(0xffffffffu, lm[h], o));
    if (lane == 0)
        #pragma unroll
        for (int h = 0; h < 8; ++h) red[wid][h] = lm[h];
    __syncthreads();
    if (tid < 8) {
        float m = red[0][tid];
        #pragma unroll
        for (int w = 1; w < 8; ++w) m = fmaxf(m, red[w][tid]);
        if (!(m >= -3.0e38f)) m = 0.f;
        smax[tid] = m;
        g_maxv[g * 8 + tid] = m;
    }
    __syncthreads();

    float mx[8], ls[8];
    #pragma unroll
    for (int h = 0; h < 8; ++h) { mx[h] = smax[h]; ls[h] = 0.f; }
    for (int r = s + tid; r < e; r += 256) {
        const float4* lp = reinterpret_cast<const float4*>(g_logits + (size_t)r * 8);
        float4 a = lp[0], b = lp[1];
        ls[0] += __expf(a.x - mx[0]); ls[1] += __expf(a.y - mx[1]);
        ls[2] += __expf(a.z - mx[2]); ls[3] += __expf(a.w - mx[3]);
        ls[4] += __expf(b.x - mx[4]); ls[5] += __expf(b.y - mx[5]);
        ls[6] += __expf(b.z - mx[6]); ls[7] += __expf(b.w - mx[7]);
    }
    #pragma unroll
    for (int h = 0; h < 8; ++h)
        #pragma unroll
        for (int o = 16; o > 0; o >>= 1)
            ls[h] += __shfl_xor_sync(0xffffffffu, ls[h], o);
    if (lane == 0)
        #pragma unroll
        for (int h = 0; h < 8; ++h) red[wid][h] = ls[h];
    __syncthreads();
    if (tid < 8) {
        float d = 0.f;
        #pragma unroll
        for (int w = 0; w < 8; ++w) d += red[w][tid];
        if (!(d > 0.f)) d = 1.f;
        g_denv[g * 8 + tid] = d;
    }
}

// ---------------------------------------------------------------------------
__global__ void k_weights(const int* __restrict__ batch,
                          float* __restrict__ w_out,
                          float* __restrict__ ent_out)
{
    int r = blockIdx.x * 256 + threadIdx.x;
    int b = batch[r];
    const float4* lp = reinterpret_cast<const float4*>(g_logits + (size_t)r * 8);
    const float4* mp = reinterpret_cast<const float4*>(g_maxv + b * 8);
    const float4* dp = reinterpret_cast<const float4*>(g_denv + b * 8);
    float4 l0 = lp[0], l1 = lp[1];
    float4 m0 = __ldg(mp), m1 = __ldg(mp + 1);
    float4 d0 = __ldg(dp), d1 = __ldg(dp + 1);

    float w[8];
    w[0] = __expf(l0.x - m0.x) / d0.x;
    w[1] = __expf(l0.y - m0.y) / d0.y;
    w[2] = __expf(l0.z - m0.z) / d0.z;
    w[3] = __expf(l0.w - m0.w) / d0.w;
    w[4] = __expf(l1.x - m1.x) / d1.x;
    w[5] = __expf(l1.y - m1.y) / d1.y;
    w[6] = __expf(l1.z - m1.z) / d1.z;
    w[7] = __expf(l1.w - m1.w) / d1.w;

    float4* op = reinterpret_cast<float4*>(w_out + (size_t)r * 8);
    op[0] = make_float4(w[0], w[1], w[2], w[3]);
    op[1] = make_float4(w[4], w[5], w[6], w[7]);

    float ent = 0.f;
    #pragma unroll
    for (int h = 0; h < 8; ++h) ent += w[h] * logf(w[h] + SM_EPS);
    #pragma unroll
    for (int o = 16; o > 0; o >>= 1)
        ent += __shfl_xor_sync(0xffffffffu, ent, o);
    if ((threadIdx.x & 31) == 0)
        atomicAdd(ent_out, -ent * (1.f / ((float)NG * (float)NHEADS)));
}

// ---------------------------------------------------------------------------
__global__ void k_scatter(const float* __restrict__ x,
                          const float* __restrict__ w,
                          float* __restrict__ gz)
{
    int g = blockIdx.x;
    int d = threadIdx.x;
    int s = g_off[g], e = g_off[g + 1];
    int h = d >> 6;
    float acc = 0.f;
    int r = s;
    for (; r + 4 <= e; r += 4) {
        float x0 = __ldg(x + (size_t)(r + 0) * HID + d);
        float x1 = __ldg(x + (size_t)(r + 1) * HID + d);
        float x2 = __ldg(x + (size_t)(r + 2) * HID + d);
        float x3 = __ldg(x + (size_t)(r + 3) * HID + d);
        float w0 = __ldg(w + (size_t)(r + 0) * 8 + h);
        float w1 = __ldg(w + (size_t)(r + 1) * 8 + h);
        float w2 = __ldg(w + (size_t)(r + 2) * 8 + h);
        float w3 = __ldg(w + (size_t)(r + 3) * 8 + h);
        acc += x0 * w0 + x1 * w1 + x2 * w2 + x3 * w3;
    }
    for (; r < e; ++r)
        acc += __ldg(x + (size_t)r * HID + d) * __ldg(w + (size_t)r * 8 + h);
    gz[(size_t)g * HID + d] = acc;
}

// ---------------------------------------------------------------------------
extern "C" void kernel_launch(void* const* d_in, const int* in_sizes, int n_in,
                              void* d_out, int out_size)
{
    (void)in_sizes; (void)n_in; (void)out_size;
    const float* x     = (const float*)d_in[0];
    const int*   batch = (const int*)  d_in[1];
    const float* gamma = (const float*)d_in[2];
    const float* beta  = (const float*)d_in[3];
    const float* W1    = (const float*)d_in[4];
    const float* b1    = (const float*)d_in[5];
    const float* W2    = (const float*)d_in[6];
    const float* b2    = (const float*)d_in[7];

    float* gz    = (float*)d_out;                    // [G, 512]
    float* w_out = gz + (size_t)NG * HID;            // [N, 8]
    float* ent   = w_out + (size_t)NROWS * NHEADS;   // [1]

    cudaFuncSetAttribute(k_logits_mma, cudaFuncAttributeMaxDynamicSharedMemorySize,
                         SMEM_TOT);

    k_init<<<1, 32>>>(ent);
    k_bounds<<<NROWS / 256, 256>>>(batch);
    k_prepw<<<HID, 256>>>(W1);
    k_logits_mma<<<NROWS / TM, NTHR, SMEM_TOT>>>(x, gamma, beta, b1, W2, b2);
    k_stats<<<NG, 256>>>();
    k_weights<<<NROWS / 256, 256>>>(batch, w_out, ent);
    k_scatter<<<NG, 512>>>(x, w_out, gz);
}